// round 12
// baseline (speedup 1.0000x reference)
#include <cuda_runtime.h>
#include <cuda_fp16.h>
#include <math.h>
#include <stdint.h>

// ---------------- problem constants ----------------
#define VOCAB   50000
#define B_DOCS  128
#define LSEQ    350
#define NGW     3
#define DIM     768
#define HID     256
#define CLS     20
#define HEADS   8
#define LAYERS  2
#define KHOPS   3
#define ALPHA   0.15f
#define NNODES  (B_DOCS*LSEQ)      // 44800
#define WIN     7

// ---------------- scratch ----------------
__device__ float g_h [NNODES*CLS];                 // node features (ping)
__device__ float g_hB[NNODES*CLS];                 // node features (pong)
__device__ __align__(1024) __half g_Wt[HID*DIM];   // W1^T fp16, pre-swizzled 16KB tiles

// ---------------- helpers ----------------
__device__ __forceinline__ uint32_t smem_u32(const void* p) {
    uint32_t a;
    asm("{ .reg .u64 t; cvta.to.shared.u64 t, %1; cvt.u32.u64 %0, t; }"
        : "=r"(a) : "l"(p));
    return a;
}
#define SWZ64(o) ((o) ^ (((o) >> 3) & 0x30))

__device__ __forceinline__ void ldsm4(uint32_t* r, uint32_t addr) {
    asm volatile("ldmatrix.sync.aligned.m8n8.x4.shared.b16 {%0,%1,%2,%3}, [%4];"
        : "=r"(r[0]), "=r"(r[1]), "=r"(r[2]), "=r"(r[3]) : "r"(addr));
}
__device__ __forceinline__ void mma16816(float* c, const uint32_t* a, const uint32_t* b) {
    asm volatile("mma.sync.aligned.m16n8k16.row.col.f32.f16.f16.f32 "
        "{%0,%1,%2,%3}, {%4,%5,%6,%7}, {%8,%9}, {%0,%1,%2,%3};"
        : "+f"(c[0]), "+f"(c[1]), "+f"(c[2]), "+f"(c[3])
        : "r"(a[0]), "r"(a[1]), "r"(a[2]), "r"(a[3]), "r"(b[0]), "r"(b[1]));
}
__device__ __forceinline__ void cpasync16(uint32_t dst, const void* src) {
    size_t gs = __cvta_generic_to_global(src);
    asm volatile("cp.async.cg.shared.global [%0], [%1], 16;"
                 :: "r"(dst), "l"(gs) : "memory");
}
#define CP_COMMIT() asm volatile("cp.async.commit_group;" ::: "memory")
#define CP_WAIT0()  asm volatile("cp.async.wait_group 0;" ::: "memory")
#define CP_WAIT1()  asm volatile("cp.async.wait_group 1;" ::: "memory")
// TMA bulk copy gmem -> smem with mbarrier transaction accounting
__device__ __forceinline__ void bulk_g2s(uint32_t dst, const void* src,
                                         uint32_t bytes, uint32_t mbar) {
    size_t gs = __cvta_generic_to_global(src);
    asm volatile(
        "cp.async.bulk.shared::cluster.global.mbarrier::complete_tx::bytes "
        "[%0], [%1], %2, [%3];"
        :: "r"(dst), "l"(gs), "r"(bytes), "r"(mbar) : "memory");
}
#define MBAR_INIT(a,c) asm volatile("mbarrier.init.shared.b64 [%0], %1;" \
    :: "r"(a), "r"(c) : "memory")
#define MBAR_EXPECT(a,tx) asm volatile( \
    "mbarrier.arrive.expect_tx.shared.b64 _, [%0], %1;" \
    :: "r"(a), "r"(tx) : "memory")
#define MBAR_WAIT(addr, par) do { \
    asm volatile("{\n\t.reg .pred P1;\n\tWAIT_%=:\n\t" \
        "mbarrier.try_wait.parity.acquire.cta.shared::cta.b64 P1, [%0], %1;\n\t" \
        "@P1 bra.uni DONE_%=;\n\tbra.uni WAIT_%=;\n\tDONE_%=:\n\t}" \
        :: "r"(addr), "r"(par) : "memory"); } while (0)
#define FENCE_ASYNC() asm volatile("fence.proxy.async.shared::cta;" ::: "memory")

// ---------------- K0: W1 -> fp16 transposed, pre-swizzled SW64 16KB tiles
__global__ __launch_bounds__(256) void k_prepw(const float* __restrict__ W1)
{
    const int k = blockIdx.x;          // 0..767
    const int n = threadIdx.x;         // 0..255
    float v = W1[k*HID + n];
    int ch = k >> 5, kk = k & 31;
    uint32_t byte = SWZ64((uint32_t)(n*64 + kk*2));
    g_Wt[(((uint32_t)ch*16384) + byte) >> 1] = __float2half_rn(v);
}

// ---------------- K1: gather + GEMM1(fp16 mma) + GEMM2 fused -------------
#define TM       160
#define KB       32
#define NCH      (DIM/KB)        // 24
#define OFF_ROWS 0
#define OFF_B1   768
#define OFF_B2   1792
#define OFF_MBAR 1920
#define OFF_AS   2048            // A fp16: 2 x 10240
#define OFF_AR   22528           // A raw fp32: 2 x 20480
#define OFF_BB   63488           // B fp16: 2 x 16384 -> 96256
#define XS_STRIDE 259
#define OFF_XS   2048
#define OFF_W2S  167808
#define OFF_HRED 188288
#define GEMM_SMEM 213888

__device__ __forceinline__ uint32_t a_addr64(uint32_t base, int row0, int kb, int lane) {
    int q = lane >> 3, lr = lane & 7;
    int row = row0 + ((q & 1) << 3) + lr;
    int k   = kb + ((q >> 1) << 3);
    return base + SWZ64((uint32_t)(row*64 + k*2));
}
__device__ __forceinline__ uint32_t b_addr64(uint32_t base, int n0, int kb, int lane) {
    int q = lane >> 3, lr = lane & 7;
    int n = n0 + ((q >> 1) << 3) + lr;
    int k = kb + ((q & 1) << 3);
    return base + SWZ64((uint32_t)(n*64 + k*2));
}

__device__ __forceinline__ void issue_A(
    uint32_t sb, const float* __restrict__ emb, const int* rows_s, int ch, int t)
{
    const uint32_t adst = sb + OFF_AR + (ch & 1)*20480;
    const int k0 = ch * KB;
    #pragma unroll
    for (int i = 0; i < 5; i++) {
        int idx = t + i*256;               // 1280 = 160m x 8c
        int m = idx >> 3, c = idx & 7;
        cpasync16(adst + (uint32_t)(m*128 + c*16),
                  emb + (size_t)rows_s[m]*DIM + k0 + c*4);
    }
}

__device__ __forceinline__ void convert_chunk(char* smc, int slot, int t)
{
    const char* raw = smc + OFF_AR + slot*20480;
    char* dH = smc + OFF_AS + slot*10240;
    #pragma unroll
    for (int i = 0; i < 5; i++) {
        int idx = t + i*256;
        int m = idx >> 3, g = idx & 7;
        float4 v = *reinterpret_cast<const float4*>(raw + m*128 + g*16);
        __half2 h0 = __float22half2_rn(make_float2(v.x, v.y));
        __half2 h1 = __float22half2_rn(make_float2(v.z, v.w));
        uint2 hv;
        hv.x = *reinterpret_cast<uint32_t*>(&h0);
        hv.y = *reinterpret_cast<uint32_t*>(&h1);
        *reinterpret_cast<uint2*>(dH + SWZ64((uint32_t)(m*64 + g*8))) = hv;
    }
}

__global__ __launch_bounds__(256, 1) void k_gemm1tc(
    const int* __restrict__ node_ids, const float* __restrict__ emb,
    const float* __restrict__ b1, const float* __restrict__ W2,
    const float* __restrict__ b2)
{
    extern __shared__ char smc[];
    const uint32_t sb = smem_u32(smc);
    const int t = threadIdx.x, lane = t & 31, wid = t >> 5;
    const int wm = wid >> 2, wn = wid & 3;       // 2 x 4 warps
    const int m0 = blockIdx.x * TM;
    int*   rows_s = (int*)(smc + OFF_ROWS);
    float* b1s    = (float*)(smc + OFF_B1);
    float* b2s    = (float*)(smc + OFF_B2);

    if (t < TM) rows_s[t] = node_ids[m0 + t];
    b1s[t] = b1[t];
    if (t < CLS) b2s[t] = b2[t];

    // zero this block's slice of g_hB (layer-0 accumulation target)
    {
        float4* zb = reinterpret_cast<float4*>(g_hB + (size_t)m0*CLS);
        #pragma unroll
        for (int i = t; i < TM*CLS/4; i += 256)
            zb[i] = make_float4(0.f, 0.f, 0.f, 0.f);
    }
    if (t == 0) {
        MBAR_INIT(sb + OFF_MBAR, 1);
        MBAR_INIT(sb + OFF_MBAR + 8, 1);
    }
    __syncthreads();
    FENCE_ASYNC();
    if (t == 0) {
        MBAR_EXPECT(sb + OFF_MBAR,     16384);   // phase for chunk 0
        MBAR_EXPECT(sb + OFF_MBAR + 8, 16384);   // phase for chunk 1
    }
    __syncthreads();

    // prologue: stage chunks 0 and 1
    issue_A(sb, emb, rows_s, 0, t); CP_COMMIT();
    issue_A(sb, emb, rows_s, 1, t); CP_COMMIT();
    if (t == 0) {
        bulk_g2s(sb + OFF_BB,         g_Wt,        16384, sb + OFF_MBAR);
        bulk_g2s(sb + OFF_BB + 16384, g_Wt + 8192, 16384, sb + OFF_MBAR + 8);
    }
    CP_WAIT1();
    MBAR_WAIT(sb + OFF_MBAR, 0u);
    if (t == 0) MBAR_EXPECT(sb + OFF_MBAR, 16384);   // arm for chunk 2
    convert_chunk(smc, 0, t);
    __syncthreads();

    float acc[5][8][4];
    #pragma unroll
    for (int mt = 0; mt < 5; mt++)
        #pragma unroll
        for (int nt = 0; nt < 8; nt++)
            #pragma unroll
            for (int q = 0; q < 4; q++) acc[mt][nt][q] = 0.f;

    for (int ch = 0; ch < NCH; ch++) {
        const int slot = ch & 1;
        const uint32_t aH = sb + OFF_AS + slot*10240;
        const uint32_t bH = sb + OFF_BB + slot*16384;
        #pragma unroll
        for (int ks = 0; ks < 2; ks++) {
            const int kb = ks*16;
            uint32_t af[5][4], bf[8][2];
            #pragma unroll
            for (int mt = 0; mt < 5; mt++)
                ldsm4(af[mt], a_addr64(aH, wm*80 + mt*16, kb, lane));
            #pragma unroll
            for (int p = 0; p < 4; p++) {
                uint32_t r[4];
                ldsm4(r, b_addr64(bH, wn*64 + p*16, kb, lane));
                bf[p*2][0]=r[0]; bf[p*2][1]=r[1];
                bf[p*2+1][0]=r[2]; bf[p*2+1][1]=r[3];
            }
            #pragma unroll
            for (int mt = 0; mt < 5; mt++)
                #pragma unroll
                for (int nt = 0; nt < 8; nt++)
                    mma16816(acc[mt][nt], af[mt], bf[nt]);
        }
        __syncthreads();                      // all reads of slot done
        if (ch + 2 < NCH) {
            issue_A(sb, emb, rows_s, ch + 2, t);
            CP_COMMIT();
            if (t == 0)
                bulk_g2s(sb + OFF_BB + slot*16384, g_Wt + (ch + 2)*8192,
                         16384, sb + OFF_MBAR + slot*8);
        }
        if (ch + 1 < NCH) {
            if (ch + 2 < NCH) CP_WAIT1(); else CP_WAIT0();
            const int s1 = (ch + 1) & 1;
            MBAR_WAIT(sb + OFF_MBAR + s1*8, (uint32_t)(((ch + 1) >> 1) & 1));
            if (t == 0 && ch + 3 < NCH)
                MBAR_EXPECT(sb + OFF_MBAR + s1*8, 16384);   // arm for ch+3
            convert_chunk(smc, s1, t);
            __syncthreads();
        }
    }
    __syncthreads();

    // ---- epilogue 1: acc -> XS with +b1, ReLU ----
    float* XS = (float*)(smc + OFF_XS);
    {
        const int lr4 = lane >> 2, lc2 = (lane & 3)*2;
        #pragma unroll
        for (int mt = 0; mt < 5; mt++) {
            #pragma unroll
            for (int nt = 0; nt < 8; nt++) {
                int r0 = wm*80 + mt*16 + lr4;
                int c0 = wn*64 + nt*8 + lc2;
                float ba = b1s[c0], bb = b1s[c0+1];
                XS[r0*XS_STRIDE + c0]       = fmaxf(acc[mt][nt][0] + ba, 0.f);
                XS[r0*XS_STRIDE + c0 + 1]   = fmaxf(acc[mt][nt][1] + bb, 0.f);
                XS[(r0+8)*XS_STRIDE + c0]   = fmaxf(acc[mt][nt][2] + ba, 0.f);
                XS[(r0+8)*XS_STRIDE + c0+1] = fmaxf(acc[mt][nt][3] + bb, 0.f);
            }
        }
    }
    float* W2S  = (float*)(smc + OFF_W2S);
    float* HRED = (float*)(smc + OFF_HRED);
    for (int i = t; i < HID*CLS; i += 256) W2S[i] = W2[i];
    __syncthreads();

    // ---- epilogue 2: h = relu(x) @ W2, (row, K-half) split over 320 workers
    for (int p = t; p < 2*TM; p += 256) {
        int half = p / TM, row = p - half*TM;
        float hacc[CLS];
        #pragma unroll
        for (int c = 0; c < CLS; c++) hacc[c] = 0.f;
        const float* xr = XS + row*XS_STRIDE + half*128;
        #pragma unroll 4
        for (int n = 0; n < 128; n++) {
            float xv = xr[n];
            const float4* w4 = reinterpret_cast<const float4*>(
                W2S + (half*128 + n)*CLS);
            #pragma unroll
            for (int q = 0; q < 5; q++) {
                float4 w = w4[q];
                hacc[q*4+0] = fmaf(xv, w.x, hacc[q*4+0]);
                hacc[q*4+1] = fmaf(xv, w.y, hacc[q*4+1]);
                hacc[q*4+2] = fmaf(xv, w.z, hacc[q*4+2]);
                hacc[q*4+3] = fmaf(xv, w.w, hacc[q*4+3]);
            }
        }
        #pragma unroll
        for (int c = 0; c < CLS; c++) HRED[p*CLS + c] = hacc[c];
    }
    __syncthreads();
    if (t < TM) {
        #pragma unroll
        for (int c = 0; c < CLS; c++)
            g_h[(m0 + t)*CLS + c] =
                HRED[t*CLS + c] + HRED[(TM + t)*CLS + c] + b2s[c];
    }
}

// ---------------- K2: zero a feature buffer ----------------
__global__ __launch_bounds__(256) void k_zero(int which)
{
    float* p = which ? g_hB : g_h;
    int i = blockIdx.x*256 + threadIdx.x;      // NNODES*CLS/4 = 224000
    reinterpret_cast<float4*>(p)[i] = make_float4(0.f, 0.f, 0.f, 0.f);
}

// ---------------- K3: fused GAT layer, [p][c] layout + row halos ---------
// Hops: paired outputs (2 adjacent p per unit) -> 8 taps serve 2 outputs.
#define GT 512
#define ZROWS 356
#define ZFL   (ZROWS*CLS)        // 7120 floats per buffer
#define OFF_zA 0
#define OFF_zB ZFL               // 7120
#define OFF_zC (2*ZFL)           // 14240
#define OFF_A0 (3*ZFL)           // 21360  (350 float4)
#define OFF_A1 (OFF_A0 + 1400)   // 22760
#define OFF_ES (OFF_A1 + 1400)   // 24160
#define OFF_ED (OFF_ES + 352)    // 24512
#define OFF_WB (OFF_ED + 352)    // 24864
#define OFF_AS2 (OFF_WB + 400)   // 25264
#define OFF_AD2 (OFF_AS2 + 20)   // 25284
#define GAT_FLOATS (OFF_AD2 + 28) // 25312
#define GAT_SMEM (GAT_FLOATS*4)   // 101248 bytes
__global__ __launch_bounds__(GT, 2) void k_gat(
    const float* __restrict__ gat_W, const float* __restrict__ a_src,
    const float* __restrict__ a_dst, int layer)
{
    extern __shared__ float gs[];
    float* zA   = gs + OFF_zA;   // z0, persists all hops
    float* zB   = gs + OFF_zB;   // h on load, then hop-0 out
    float* zC   = gs + OFF_zC;   // hop-1 out
    float* att0 = gs + OFF_A0;
    float* att1 = gs + OFF_A1;
    float* esb  = gs + OFF_ES;
    float* edb  = gs + OFF_ED;
    float* Wb   = gs + OFF_WB;
    float* asb  = gs + OFF_AS2;
    float* adb  = gs + OFF_AD2;
    const int t = threadIdx.x;
    const int hd = blockIdx.x & 7, doc = blockIdx.x >> 3;
    const float* src = (layer == 0) ? g_h : g_hB;
    float*       dst = (layer == 0) ? g_hB : g_h;

    // load h straight into zB rows 3..352 (float4 copy, no transpose)
    const float4* hg = reinterpret_cast<const float4*>(src + (size_t)doc*LSEQ*CLS);
    float4* zB4 = reinterpret_cast<float4*>(zB);
    for (int i = t; i < LSEQ*CLS/4; i += GT) zB4[i + 15] = hg[i];
    const float* Wg = gat_W + ((size_t)layer*HEADS + hd)*CLS*CLS;
    for (int i = t; i < CLS*CLS; i += GT) Wb[i] = Wg[i];
    if (t >= GT-32 && t < GT-32+CLS) {
        int c = t - (GT-32);
        asb[c] = a_src[(layer*HEADS + hd)*CLS + c];
        adb[c] = a_dst[(layer*HEADS + hd)*CLS + c];
    }
    // zero halos (rows -3..-1 and 350..352) of all three buffers
    if (t >= GT-128 && t < GT-128+90) {
        int r0 = t - (GT-128);
        int buf = r0 / 30, r = r0 % 30;
        float4* z = reinterpret_cast<float4*>(gs + buf*ZFL);
        int idx = (r < 15) ? r : (ZFL/4 - 30 + r);
        z[idx] = make_float4(0.f, 0.f, 0.f, 0.f);
    }
    __syncthreads();

    // projection: zA[p+3][c] = sum_c2 h[p][c2] * W[c2][c]; es/ed scores
    for (int p = t; p < LSEQ; p += GT) {
        const float4* hr4 = reinterpret_cast<const float4*>(zB + (p+3)*CLS);
        float hv[CLS];
        #pragma unroll
        for (int q = 0; q < 5; q++) {
            float4 v = hr4[q];
            hv[q*4+0] = v.x; hv[q*4+1] = v.y; hv[q*4+2] = v.z; hv[q*4+3] = v.w;
        }
        float zr[CLS];
        #pragma unroll
        for (int c = 0; c < CLS; c++) zr[c] = 0.f;
        #pragma unroll
        for (int c2 = 0; c2 < CLS; c2++) {
            #pragma unroll
            for (int c = 0; c < CLS; c++)
                zr[c] = fmaf(hv[c2], Wb[c2*CLS + c], zr[c]);
        }
        float es = 0.f, ed = 0.f;
        #pragma unroll
        for (int c = 0; c < CLS; c++) {
            es = fmaf(zr[c], asb[c], es);
            ed = fmaf(zr[c], adb[c], ed);
        }
        esb[p] = es; edb[p] = ed;
        float4* za4 = reinterpret_cast<float4*>(zA + (p+3)*CLS);
        #pragma unroll
        for (int q = 0; q < 5; q++)
            za4[q] = make_float4(zr[q*4+0], zr[q*4+1], zr[q*4+2], zr[q*4+3]);
    }
    __syncthreads();

    // banded softmax -> att planes (float4 rows)
    for (int p = t; p < LSEQ; p += GT) {
        float ed = edb[p];
        float e[WIN], m = -1e30f;
        #pragma unroll
        for (int w = 0; w < WIN; w++) {
            int j = p - NGW + w;
            bool valid = (j >= 0) & (j < LSEQ);
            int jj = valid ? j : p;
            float ev = esb[jj] + ed;
            ev = ev > 0.f ? ev : 0.2f*ev;
            e[w] = valid ? ev : -1e30f;
            m = fmaxf(m, e[w]);
        }
        float ex[WIN], s = 0.f;
        #pragma unroll
        for (int w = 0; w < WIN; w++) {
            ex[w] = (e[w] > -1e29f) ? expf(e[w] - m) : 0.f;
            s += ex[w];
        }
        float inv = 1.f / (s + 1e-9f);
        reinterpret_cast<float4*>(att0)[p] =
            make_float4(ex[0]*inv, ex[1]*inv, ex[2]*inv, ex[3]*inv);
        reinterpret_cast<float4*>(att1)[p] =
            make_float4(ex[4]*inv, ex[5]*inv, ex[6]*inv, 0.f);
    }
    __syncthreads();

    // hops: zA -> zB -> zC -> gmem atomics; paired outputs share taps
    float* dsb = dst + (size_t)doc*LSEQ*CLS;
    const float4* att0_4 = reinterpret_cast<const float4*>(att0);
    const float4* att1_4 = reinterpret_cast<const float4*>(att1);
    const float4* zA4c   = reinterpret_cast<const float4*>(zA);
    #pragma unroll
    for (int hop = 0; hop < KHOPS; hop++) {
        const float4* zin4  = reinterpret_cast<const float4*>(
            (hop == 0) ? zA : ((hop == 1) ? zB : zC));
        float4* zout4 = reinterpret_cast<float4*>((hop == 0) ? zB : zC);
        for (int j = t; j < 875; j += GT) {       // 875 = 175 pairs x 5 groups
            const int g  = j % 5;
            const int pp = j / 5;
            const int p0 = pp * 2;
            const float4* zi = zin4 + p0*5 + g;
            // taps for both outputs: buffer rows p0 .. p0+7
            float4 w0 = zi[0],  w1 = zi[5],  w2 = zi[10], w3 = zi[15];
            float4 w4 = zi[20], w5 = zi[25], w6 = zi[30], w7 = zi[35];
            // output p0
            {
                float4 a0 = att0_4[p0], a1 = att1_4[p0];
                float4 acc;
                acc.x = a0.x*w0.x; acc.y = a0.x*w0.y; acc.z = a0.x*w0.z; acc.w = a0.x*w0.w;
                acc.x = fmaf(a0.y, w1.x, acc.x); acc.y = fmaf(a0.y, w1.y, acc.y);
                acc.z = fmaf(a0.y, w1.z, acc.z); acc.w = fmaf(a0.y, w1.w, acc.w);
                acc.x = fmaf(a0.z, w2.x, acc.x); acc.y = fmaf(a0.z, w2.y, acc.y);
                acc.z = fmaf(a0.z, w2.z, acc.z); acc.w = fmaf(a0.z, w2.w, acc.w);
                acc.x = fmaf(a0.w, w3.x, acc.x); acc.y = fmaf(a0.w, w3.y, acc.y);
                acc.z = fmaf(a0.w, w3.z, acc.z); acc.w = fmaf(a0.w, w3.w, acc.w);
                acc.x = fmaf(a1.x, w4.x, acc.x); acc.y = fmaf(a1.x, w4.y, acc.y);
                acc.z = fmaf(a1.x, w4.z, acc.z); acc.w = fmaf(a1.x, w4.w, acc.w);
                acc.x = fmaf(a1.y, w5.x, acc.x); acc.y = fmaf(a1.y, w5.y, acc.y);
                acc.z = fmaf(a1.y, w5.z, acc.z); acc.w = fmaf(a1.y, w5.w, acc.w);
                acc.x = fmaf(a1.z, w6.x, acc.x); acc.y = fmaf(a1.z, w6.y, acc.y);
                acc.z = fmaf(a1.z, w6.z, acc.z); acc.w = fmaf(a1.z, w6.w, acc.w);
                float4 z0v = zA4c[(p0+3)*5 + g];
                float4 v;
                v.x = fmaf(1.f - ALPHA, acc.x, ALPHA*z0v.x);
                v.y = fmaf(1.f - ALPHA, acc.y, ALPHA*z0v.y);
                v.z = fmaf(1.f - ALPHA, acc.z, ALPHA*z0v.z);
                v.w = fmaf(1.f - ALPHA, acc.w, ALPHA*z0v.w);
                if (hop == KHOPS-1) {
                    float* o = dsb + p0*CLS + g*4;
                    atomicAdd(o+0, ((v.x > 0.f) ? v.x : expm1f(v.x)) * (1.f/HEADS));
                    atomicAdd(o+1, ((v.y > 0.f) ? v.y : expm1f(v.y)) * (1.f/HEADS));
                    atomicAdd(o+2, ((v.z > 0.f) ? v.z : expm1f(v.z)) * (1.f/HEADS));
                    atomicAdd(o+3, ((v.w > 0.f) ? v.w : expm1f(v.w)) * (1.f/HEADS));
                } else {
                    zout4[(p0+3)*5 + g] = v;
                }
            }
            // output p0+1 (taps w1..w7)
            {
                const int p1 = p0 + 1;
                float4 a0 = att0_4[p1], a1 = att1_4[p1];
                float4 acc;
                acc.x = a0.x*w1.x; acc.y = a0.x*w1.y; acc.z = a0.x*w1.z; acc.w = a0.x*w1.w;
                acc.x = fmaf(a0.y, w2.x, acc.x); acc.y = fmaf(a0.y, w2.y, acc.y);
                acc.z = fmaf(a0.y, w2.z, acc.z); acc.w = fmaf(a0.y, w2.w, acc.w);
                acc.x = fmaf(a0.z, w3.x, acc.x); acc.y = fmaf(a0.z, w3.y, acc.y);
                acc.z = fmaf(a0.z, w3.z, acc.z); acc.w = fmaf(a0.z, w3.w, acc.w);
                acc.x = fmaf(a0.w, w4.x, acc.x); acc.y = fmaf(a0.w, w4.y, acc.y);
                acc.z = fmaf(a0.w, w4.z, acc.z); acc.w = fmaf(a0.w, w4.w, acc.w);
                acc.x = fmaf(a1.x, w5.x, acc.x); acc.y = fmaf(a1.x, w5.y, acc.y);
                acc.z = fmaf(a1.x, w5.z, acc.z); acc.w = fmaf(a1.x, w5.w, acc.w);
                acc.x = fmaf(a1.y, w6.x, acc.x); acc.y = fmaf(a1.y, w6.y, acc.y);
                acc.z = fmaf(a1.y, w6.z, acc.z); acc.w = fmaf(a1.y, w6.w, acc.w);
                acc.x = fmaf(a1.z, w7.x, acc.x); acc.y = fmaf(a1.z, w7.y, acc.y);
                acc.z = fmaf(a1.z, w7.z, acc.z); acc.w = fmaf(a1.z, w7.w, acc.w);
                float4 z0v = zA4c[(p1+3)*5 + g];
                float4 v;
                v.x = fmaf(1.f - ALPHA, acc.x, ALPHA*z0v.x);
                v.y = fmaf(1.f - ALPHA, acc.y, ALPHA*z0v.y);
                v.z = fmaf(1.f - ALPHA, acc.z, ALPHA*z0v.z);
                v.w = fmaf(1.f - ALPHA, acc.w, ALPHA*z0v.w);
                if (hop == KHOPS-1) {
                    float* o = dsb + p1*CLS + g*4;
                    atomicAdd(o+0, ((v.x > 0.f) ? v.x : expm1f(v.x)) * (1.f/HEADS));
                    atomicAdd(o+1, ((v.y > 0.f) ? v.y : expm1f(v.y)) * (1.f/HEADS));
                    atomicAdd(o+2, ((v.z > 0.f) ? v.z : expm1f(v.z)) * (1.f/HEADS));
                    atomicAdd(o+3, ((v.w > 0.f) ? v.w : expm1f(v.w)) * (1.f/HEADS));
                } else {
                    zout4[(p1+3)*5 + g] = v;
                }
            }
        }
        if (hop < KHOPS-1) __syncthreads();
    }
}

// ---------------- K4: gated readout ----------------
__global__ __launch_bounds__(256) void k_readout(
    const float* __restrict__ w_gate, const float* __restrict__ b_gate,
    float* __restrict__ out)
{
    __shared__ float wg[CLS];
    __shared__ float sred[240];
    const int t = threadIdx.x;
    if (t < CLS) wg[t] = w_gate[t];
    __syncthreads();
    const int doc = blockIdx.x;
    const float bg = b_gate[0];
    float acc = 0.f;
    if (t < 240) {
        int c = t % CLS, r = t / CLS;
        for (int p = r; p < LSEQ; p += 12) {
            const float* hr = g_h + (doc*LSEQ + p)*CLS;
            float dot = bg;
            #pragma unroll
            for (int k = 0; k < CLS; k++) dot = fmaf(hr[k], wg[k], dot);
            float gate = 1.f / (1.f + expf(-dot));
            acc = fmaf(gate, hr[c], acc);
        }
        sred[t] = acc;
    }
    __syncthreads();
    if (t < CLS) {
        float s = 0.f;
        #pragma unroll
        for (int r = 0; r < 12; r++) s += sred[r*CLS + t];
        out[doc*CLS + t] = s;
    }
}

// ---------------- launch ----------------
extern "C" void kernel_launch(void* const* d_in, const int* in_sizes, int n_in,
                              void* d_out, int out_size)
{
    const int*   node_ids = (const int*)  d_in[0];
    const float* emb    = (const float*) d_in[4];
    const float* W1     = (const float*) d_in[5];
    const float* b1     = (const float*) d_in[6];
    const float* W2     = (const float*) d_in[7];
    const float* b2     = (const float*) d_in[8];
    const float* gat_W  = (const float*) d_in[9];
    const float* a_src  = (const float*) d_in[10];
    const float* a_dst  = (const float*) d_in[11];
    const float* w_gate = (const float*) d_in[12];
    const float* b_gate = (const float*) d_in[13];
    float* out = (float*)d_out;

    cudaFuncSetAttribute(k_gemm1tc,
        cudaFuncAttributeMaxDynamicSharedMemorySize, GEMM_SMEM);
    cudaFuncSetAttribute(k_gat,
        cudaFuncAttributeMaxDynamicSharedMemorySize, GAT_SMEM);

    k_prepw<<<DIM, 256>>>(W1);                                           // 768
    k_gemm1tc<<<NNODES/TM, 256, GEMM_SMEM>>>(node_ids, emb, b1, W2, b2); // 280
    for (int l = 0; l < LAYERS; l++) {
        if (l > 0) k_zero<<<NNODES*CLS/1024, 256>>>(0);                  // zero g_h
        k_gat<<<B_DOCS*HEADS, GT, GAT_SMEM>>>(gat_W, a_src, a_dst, l);   // 1024
    }
    k_readout<<<B_DOCS, 256>>>(w_gate, b_gate, out);
}

// round 13
// speedup vs baseline: 1.0975x; 1.0975x over previous
#include <cuda_runtime.h>
#include <cuda_fp16.h>
#include <math.h>
#include <stdint.h>

// ---------------- problem constants ----------------
#define VOCAB   50000
#define B_DOCS  128
#define LSEQ    350
#define NGW     3
#define DIM     768
#define HID     256
#define CLS     20
#define HEADS   8
#define LAYERS  2
#define KHOPS   3
#define ALPHA   0.15f
#define NNODES  (B_DOCS*LSEQ)      // 44800
#define WIN     7

// ---------------- scratch ----------------
__device__ float g_h [NNODES*CLS];                 // node features (ping)
__device__ float g_hB[NNODES*CLS];                 // node features (pong)
__device__ __align__(1024) __half g_Wt[HID*DIM];   // W1^T fp16, pre-swizzled 16KB tiles

// ---------------- helpers ----------------
__device__ __forceinline__ uint32_t smem_u32(const void* p) {
    uint32_t a;
    asm("{ .reg .u64 t; cvta.to.shared.u64 t, %1; cvt.u32.u64 %0, t; }"
        : "=r"(a) : "l"(p));
    return a;
}
#define SWZ64(o) ((o) ^ (((o) >> 3) & 0x30))

__device__ __forceinline__ void ldsm4(uint32_t* r, uint32_t addr) {
    asm volatile("ldmatrix.sync.aligned.m8n8.x4.shared.b16 {%0,%1,%2,%3}, [%4];"
        : "=r"(r[0]), "=r"(r[1]), "=r"(r[2]), "=r"(r[3]) : "r"(addr));
}
__device__ __forceinline__ void mma16816(float* c, const uint32_t* a, const uint32_t* b) {
    asm volatile("mma.sync.aligned.m16n8k16.row.col.f32.f16.f16.f32 "
        "{%0,%1,%2,%3}, {%4,%5,%6,%7}, {%8,%9}, {%0,%1,%2,%3};"
        : "+f"(c[0]), "+f"(c[1]), "+f"(c[2]), "+f"(c[3])
        : "r"(a[0]), "r"(a[1]), "r"(a[2]), "r"(a[3]), "r"(b[0]), "r"(b[1]));
}
__device__ __forceinline__ void cpasync16(uint32_t dst, const void* src) {
    size_t gs = __cvta_generic_to_global(src);
    asm volatile("cp.async.cg.shared.global [%0], [%1], 16;"
                 :: "r"(dst), "l"(gs) : "memory");
}
#define CP_COMMIT() asm volatile("cp.async.commit_group;" ::: "memory")
#define CP_WAIT0()  asm volatile("cp.async.wait_group 0;" ::: "memory")
#define CP_WAIT1()  asm volatile("cp.async.wait_group 1;" ::: "memory")
#define CP_WAIT2()  asm volatile("cp.async.wait_group 2;" ::: "memory")
// TMA bulk copy gmem -> smem with mbarrier transaction accounting
__device__ __forceinline__ void bulk_g2s(uint32_t dst, const void* src,
                                         uint32_t bytes, uint32_t mbar) {
    size_t gs = __cvta_generic_to_global(src);
    asm volatile(
        "cp.async.bulk.shared::cluster.global.mbarrier::complete_tx::bytes "
        "[%0], [%1], %2, [%3];"
        :: "r"(dst), "l"(gs), "r"(bytes), "r"(mbar) : "memory");
}
#define MBAR_INIT(a,c) asm volatile("mbarrier.init.shared.b64 [%0], %1;" \
    :: "r"(a), "r"(c) : "memory")
#define MBAR_EXPECT(a,tx) asm volatile( \
    "mbarrier.arrive.expect_tx.shared.b64 _, [%0], %1;" \
    :: "r"(a), "r"(tx) : "memory")
#define MBAR_WAIT(addr, par) do { \
    asm volatile("{\n\t.reg .pred P1;\n\tWAIT_%=:\n\t" \
        "mbarrier.try_wait.parity.acquire.cta.shared::cta.b64 P1, [%0], %1;\n\t" \
        "@P1 bra.uni DONE_%=;\n\tbra.uni WAIT_%=;\n\tDONE_%=:\n\t}" \
        :: "r"(addr), "r"(par) : "memory"); } while (0)
#define FENCE_ASYNC() asm volatile("fence.proxy.async.shared::cta;" ::: "memory")

// ---------------- K0: W1 -> fp16 transposed, pre-swizzled SW64 16KB tiles
__global__ __launch_bounds__(256) void k_prepw(const float* __restrict__ W1)
{
    const int k = blockIdx.x;          // 0..767
    const int n = threadIdx.x;         // 0..255
    float v = W1[k*HID + n];
    int ch = k >> 5, kk = k & 31;
    uint32_t byte = SWZ64((uint32_t)(n*64 + kk*2));
    g_Wt[(((uint32_t)ch*16384) + byte) >> 1] = __float2half_rn(v);
}

// ---------------- K1: gather + GEMM1(fp16 mma) + GEMM2 fused -------------
// 3-stage pipeline: A cp.async gather + convert; B one 16KB bulk per chunk.
#define TM       160
#define KB       32
#define NCH      (DIM/KB)        // 24
#define OFF_ROWS 0
#define OFF_B1   768
#define OFF_B2   1792
#define OFF_MBAR 1920            // 3 x 8B mbarriers
#define OFF_AS   2048            // A fp16:   3 x 10240 -> 32768
#define OFF_AR   32768           // A raw:    3 x 20480 -> 94208
#define OFF_BB   94208           // B fp16:   3 x 16384 -> 143360
#define XS_STRIDE 259
#define OFF_XS   2048
#define OFF_W2S  167808
#define OFF_HRED 188288
#define GEMM_SMEM 213888

__device__ __forceinline__ uint32_t a_addr64(uint32_t base, int row0, int kb, int lane) {
    int q = lane >> 3, lr = lane & 7;
    int row = row0 + ((q & 1) << 3) + lr;
    int k   = kb + ((q >> 1) << 3);
    return base + SWZ64((uint32_t)(row*64 + k*2));
}
__device__ __forceinline__ uint32_t b_addr64(uint32_t base, int n0, int kb, int lane) {
    int q = lane >> 3, lr = lane & 7;
    int n = n0 + ((q >> 1) << 3) + lr;
    int k = kb + ((q & 1) << 3);
    return base + SWZ64((uint32_t)(n*64 + k*2));
}

__device__ __forceinline__ void issue_A(
    uint32_t sb, const float* __restrict__ emb, const int* rows_s, int ch, int t)
{
    const uint32_t adst = sb + OFF_AR + (uint32_t)(ch % 3)*20480;
    const int k0 = ch * KB;
    #pragma unroll
    for (int i = 0; i < 5; i++) {
        int idx = t + i*256;               // 1280 = 160m x 8c
        int m = idx >> 3, c = idx & 7;
        cpasync16(adst + (uint32_t)(m*128 + c*16),
                  emb + (size_t)rows_s[m]*DIM + k0 + c*4);
    }
}

__device__ __forceinline__ void convert_chunk(char* smc, int slot, int t)
{
    const char* raw = smc + OFF_AR + slot*20480;
    char* dH = smc + OFF_AS + slot*10240;
    #pragma unroll
    for (int i = 0; i < 5; i++) {
        int idx = t + i*256;
        int m = idx >> 3, g = idx & 7;
        float4 v = *reinterpret_cast<const float4*>(raw + m*128 + g*16);
        __half2 h0 = __float22half2_rn(make_float2(v.x, v.y));
        __half2 h1 = __float22half2_rn(make_float2(v.z, v.w));
        uint2 hv;
        hv.x = *reinterpret_cast<uint32_t*>(&h0);
        hv.y = *reinterpret_cast<uint32_t*>(&h1);
        *reinterpret_cast<uint2*>(dH + SWZ64((uint32_t)(m*64 + g*8))) = hv;
    }
}

__global__ __launch_bounds__(256, 1) void k_gemm1tc(
    const int* __restrict__ node_ids, const float* __restrict__ emb,
    const float* __restrict__ b1, const float* __restrict__ W2,
    const float* __restrict__ b2)
{
    extern __shared__ char smc[];
    const uint32_t sb = smem_u32(smc);
    const int t = threadIdx.x, lane = t & 31, wid = t >> 5;
    const int wm = wid >> 2, wn = wid & 3;       // 2 x 4 warps
    const int m0 = blockIdx.x * TM;
    int*   rows_s = (int*)(smc + OFF_ROWS);
    float* b1s    = (float*)(smc + OFF_B1);
    float* b2s    = (float*)(smc + OFF_B2);

    if (t < TM) rows_s[t] = node_ids[m0 + t];
    b1s[t] = b1[t];
    if (t < CLS) b2s[t] = b2[t];

    // zero this block's slice of g_hB (layer-0 accumulation target)
    {
        float4* zb = reinterpret_cast<float4*>(g_hB + (size_t)m0*CLS);
        #pragma unroll
        for (int i = t; i < TM*CLS/4; i += 256)
            zb[i] = make_float4(0.f, 0.f, 0.f, 0.f);
    }
    if (t == 0) {
        MBAR_INIT(sb + OFF_MBAR,      1);
        MBAR_INIT(sb + OFF_MBAR + 8,  1);
        MBAR_INIT(sb + OFF_MBAR + 16, 1);
    }
    __syncthreads();
    FENCE_ASYNC();
    if (t == 0) {
        MBAR_EXPECT(sb + OFF_MBAR,      16384);   // chunk 0
        MBAR_EXPECT(sb + OFF_MBAR + 8,  16384);   // chunk 1
        MBAR_EXPECT(sb + OFF_MBAR + 16, 16384);   // chunk 2
    }
    __syncthreads();

    // prologue: stage chunks 0,1,2
    issue_A(sb, emb, rows_s, 0, t); CP_COMMIT();
    issue_A(sb, emb, rows_s, 1, t); CP_COMMIT();
    issue_A(sb, emb, rows_s, 2, t); CP_COMMIT();
    if (t == 0) {
        bulk_g2s(sb + OFF_BB,         g_Wt,         16384, sb + OFF_MBAR);
        bulk_g2s(sb + OFF_BB + 16384, g_Wt + 8192,  16384, sb + OFF_MBAR + 8);
        bulk_g2s(sb + OFF_BB + 32768, g_Wt + 16384, 16384, sb + OFF_MBAR + 16);
    }
    CP_WAIT2();
    MBAR_WAIT(sb + OFF_MBAR, 0u);
    if (t == 0) MBAR_EXPECT(sb + OFF_MBAR, 16384);   // arm chunk 3
    convert_chunk(smc, 0, t);
    __syncthreads();

    float acc[5][8][4];
    #pragma unroll
    for (int mt = 0; mt < 5; mt++)
        #pragma unroll
        for (int nt = 0; nt < 8; nt++)
            #pragma unroll
            for (int q = 0; q < 4; q++) acc[mt][nt][q] = 0.f;

    for (int ch = 0; ch < NCH; ch++) {
        const int slot = ch % 3;
        const uint32_t aH = sb + OFF_AS + slot*10240;
        const uint32_t bH = sb + OFF_BB + slot*16384;
        #pragma unroll
        for (int ks = 0; ks < 2; ks++) {
            const int kb = ks*16;
            uint32_t af[5][4], bf[8][2];
            #pragma unroll
            for (int mt = 0; mt < 5; mt++)
                ldsm4(af[mt], a_addr64(aH, wm*80 + mt*16, kb, lane));
            #pragma unroll
            for (int p = 0; p < 4; p++) {
                uint32_t r[4];
                ldsm4(r, b_addr64(bH, wn*64 + p*16, kb, lane));
                bf[p*2][0]=r[0]; bf[p*2][1]=r[1];
                bf[p*2+1][0]=r[2]; bf[p*2+1][1]=r[3];
            }
            #pragma unroll
            for (int mt = 0; mt < 5; mt++)
                #pragma unroll
                for (int nt = 0; nt < 8; nt++)
                    mma16816(acc[mt][nt], af[mt], bf[nt]);
        }
        __syncthreads();                      // all reads of slot done
        if (ch + 3 < NCH) {                   // refill this slot with ch+3
            issue_A(sb, emb, rows_s, ch + 3, t);
            CP_COMMIT();
            if (t == 0)
                bulk_g2s(sb + OFF_BB + slot*16384, g_Wt + (ch + 3)*8192,
                         16384, sb + OFF_MBAR + slot*8);
        }
        if (ch + 1 < NCH) {
            if      (ch + 3 < NCH) CP_WAIT2();
            else if (ch + 2 < NCH) CP_WAIT1();
            else                   CP_WAIT0();
            const int s1 = (ch + 1) % 3;
            MBAR_WAIT(sb + OFF_MBAR + s1*8, (uint32_t)(((ch + 1) / 3) & 1));
            if (t == 0 && ch + 4 < NCH)
                MBAR_EXPECT(sb + OFF_MBAR + s1*8, 16384);   // arm ch+4
            convert_chunk(smc, s1, t);
            __syncthreads();
        }
    }
    __syncthreads();

    // ---- epilogue 1: acc -> XS with +b1, ReLU ----
    float* XS = (float*)(smc + OFF_XS);
    {
        const int lr4 = lane >> 2, lc2 = (lane & 3)*2;
        #pragma unroll
        for (int mt = 0; mt < 5; mt++) {
            #pragma unroll
            for (int nt = 0; nt < 8; nt++) {
                int r0 = wm*80 + mt*16 + lr4;
                int c0 = wn*64 + nt*8 + lc2;
                float ba = b1s[c0], bb = b1s[c0+1];
                XS[r0*XS_STRIDE + c0]       = fmaxf(acc[mt][nt][0] + ba, 0.f);
                XS[r0*XS_STRIDE + c0 + 1]   = fmaxf(acc[mt][nt][1] + bb, 0.f);
                XS[(r0+8)*XS_STRIDE + c0]   = fmaxf(acc[mt][nt][2] + ba, 0.f);
                XS[(r0+8)*XS_STRIDE + c0+1] = fmaxf(acc[mt][nt][3] + bb, 0.f);
            }
        }
    }
    float* W2S  = (float*)(smc + OFF_W2S);
    float* HRED = (float*)(smc + OFF_HRED);
    for (int i = t; i < HID*CLS; i += 256) W2S[i] = W2[i];
    __syncthreads();

    // ---- epilogue 2: h = relu(x) @ W2, (row, K-half) split over 320 workers
    for (int p = t; p < 2*TM; p += 256) {
        int half = p / TM, row = p - half*TM;
        float hacc[CLS];
        #pragma unroll
        for (int c = 0; c < CLS; c++) hacc[c] = 0.f;
        const float* xr = XS + row*XS_STRIDE + half*128;
        #pragma unroll 4
        for (int n = 0; n < 128; n++) {
            float xv = xr[n];
            const float4* w4 = reinterpret_cast<const float4*>(
                W2S + (half*128 + n)*CLS);
            #pragma unroll
            for (int q = 0; q < 5; q++) {
                float4 w = w4[q];
                hacc[q*4+0] = fmaf(xv, w.x, hacc[q*4+0]);
                hacc[q*4+1] = fmaf(xv, w.y, hacc[q*4+1]);
                hacc[q*4+2] = fmaf(xv, w.z, hacc[q*4+2]);
                hacc[q*4+3] = fmaf(xv, w.w, hacc[q*4+3]);
            }
        }
        #pragma unroll
        for (int c = 0; c < CLS; c++) HRED[p*CLS + c] = hacc[c];
    }
    __syncthreads();
    if (t < TM) {
        #pragma unroll
        for (int c = 0; c < CLS; c++)
            g_h[(m0 + t)*CLS + c] =
                HRED[t*CLS + c] + HRED[(TM + t)*CLS + c] + b2s[c];
    }
}

// ---------------- K2: zero a feature buffer ----------------
__global__ __launch_bounds__(256) void k_zero(int which)
{
    float* p = which ? g_hB : g_h;
    int i = blockIdx.x*256 + threadIdx.x;      // NNODES*CLS/4 = 224000
    reinterpret_cast<float4*>(p)[i] = make_float4(0.f, 0.f, 0.f, 0.f);
}

// ---------------- K3: fused GAT layer (R10-proven flat hop) --------------
#define GT 512
#define ZROWS 356
#define ZFL   (ZROWS*CLS)        // 7120 floats per buffer
#define OFF_zA 0
#define OFF_zB ZFL               // 7120
#define OFF_zC (2*ZFL)           // 14240
#define OFF_A0 (3*ZFL)           // 21360  (350 float4)
#define OFF_A1 (OFF_A0 + 1400)   // 22760
#define OFF_ES (OFF_A1 + 1400)   // 24160
#define OFF_ED (OFF_ES + 352)    // 24512
#define OFF_WB (OFF_ED + 352)    // 24864
#define OFF_AS2 (OFF_WB + 400)   // 25264
#define OFF_AD2 (OFF_AS2 + 20)   // 25284
#define GAT_FLOATS (OFF_AD2 + 28) // 25312
#define GAT_SMEM (GAT_FLOATS*4)   // 101248 bytes
__global__ __launch_bounds__(GT, 2) void k_gat(
    const float* __restrict__ gat_W, const float* __restrict__ a_src,
    const float* __restrict__ a_dst, int layer)
{
    extern __shared__ float gs[];
    float* zA   = gs + OFF_zA;   // z0, persists all hops
    float* zB   = gs + OFF_zB;   // h on load, then hop-0 out
    float* zC   = gs + OFF_zC;   // hop-1 out
    float* att0 = gs + OFF_A0;
    float* att1 = gs + OFF_A1;
    float* esb  = gs + OFF_ES;
    float* edb  = gs + OFF_ED;
    float* Wb   = gs + OFF_WB;
    float* asb  = gs + OFF_AS2;
    float* adb  = gs + OFF_AD2;
    const int t = threadIdx.x;
    const int hd = blockIdx.x & 7, doc = blockIdx.x >> 3;
    const float* src = (layer == 0) ? g_h : g_hB;
    float*       dst = (layer == 0) ? g_hB : g_h;

    // load h straight into zB rows 3..352 (float4 copy, no transpose)
    const float4* hg = reinterpret_cast<const float4*>(src + (size_t)doc*LSEQ*CLS);
    float4* zB4 = reinterpret_cast<float4*>(zB);
    for (int i = t; i < LSEQ*CLS/4; i += GT) zB4[i + 15] = hg[i];
    const float* Wg = gat_W + ((size_t)layer*HEADS + hd)*CLS*CLS;
    for (int i = t; i < CLS*CLS; i += GT) Wb[i] = Wg[i];
    if (t >= GT-32 && t < GT-32+CLS) {
        int c = t - (GT-32);
        asb[c] = a_src[(layer*HEADS + hd)*CLS + c];
        adb[c] = a_dst[(layer*HEADS + hd)*CLS + c];
    }
    // zero halos (rows -3..-1 and 350..352) of all three buffers
    if (t >= GT-128 && t < GT-128+90) {
        int r0 = t - (GT-128);
        int buf = r0 / 30, r = r0 % 30;
        float4* z = reinterpret_cast<float4*>(gs + buf*ZFL);
        int idx = (r < 15) ? r : (ZFL/4 - 30 + r);
        z[idx] = make_float4(0.f, 0.f, 0.f, 0.f);
    }
    __syncthreads();

    // projection: zA[p+3][c] = sum_c2 h[p][c2] * W[c2][c]; es/ed scores
    for (int p = t; p < LSEQ; p += GT) {
        const float4* hr4 = reinterpret_cast<const float4*>(zB + (p+3)*CLS);
        float hv[CLS];
        #pragma unroll
        for (int q = 0; q < 5; q++) {
            float4 v = hr4[q];
            hv[q*4+0] = v.x; hv[q*4+1] = v.y; hv[q*4+2] = v.z; hv[q*4+3] = v.w;
        }
        float zr[CLS];
        #pragma unroll
        for (int c = 0; c < CLS; c++) zr[c] = 0.f;
        #pragma unroll
        for (int c2 = 0; c2 < CLS; c2++) {
            #pragma unroll
            for (int c = 0; c < CLS; c++)
                zr[c] = fmaf(hv[c2], Wb[c2*CLS + c], zr[c]);
        }
        float es = 0.f, ed = 0.f;
        #pragma unroll
        for (int c = 0; c < CLS; c++) {
            es = fmaf(zr[c], asb[c], es);
            ed = fmaf(zr[c], adb[c], ed);
        }
        esb[p] = es; edb[p] = ed;
        float4* za4 = reinterpret_cast<float4*>(zA + (p+3)*CLS);
        #pragma unroll
        for (int q = 0; q < 5; q++)
            za4[q] = make_float4(zr[q*4+0], zr[q*4+1], zr[q*4+2], zr[q*4+3]);
    }
    __syncthreads();

    // banded softmax -> att planes (float4 rows)
    for (int p = t; p < LSEQ; p += GT) {
        float ed = edb[p];
        float e[WIN], m = -1e30f;
        #pragma unroll
        for (int w = 0; w < WIN; w++) {
            int j = p - NGW + w;
            bool valid = (j >= 0) & (j < LSEQ);
            int jj = valid ? j : p;
            float ev = esb[jj] + ed;
            ev = ev > 0.f ? ev : 0.2f*ev;
            e[w] = valid ? ev : -1e30f;
            m = fmaxf(m, e[w]);
        }
        float ex[WIN], s = 0.f;
        #pragma unroll
        for (int w = 0; w < WIN; w++) {
            ex[w] = (e[w] > -1e29f) ? expf(e[w] - m) : 0.f;
            s += ex[w];
        }
        float inv = 1.f / (s + 1e-9f);
        reinterpret_cast<float4*>(att0)[p] =
            make_float4(ex[0]*inv, ex[1]*inv, ex[2]*inv, ex[3]*inv);
        reinterpret_cast<float4*>(att1)[p] =
            make_float4(ex[4]*inv, ex[5]*inv, ex[6]*inv, 0.f);
    }
    __syncthreads();

    // hops: zA -> zB -> zC -> gmem atomics; all accesses float4
    float* dsb = dst + (size_t)doc*LSEQ*CLS;
    #pragma unroll
    for (int hop = 0; hop < KHOPS; hop++) {
        const float4* zin4  = reinterpret_cast<const float4*>(
            (hop == 0) ? zA : ((hop == 1) ? zB : zC));
        float4* zout4 = reinterpret_cast<float4*>((hop == 0) ? zB : zC);
        for (int j = t; j < LSEQ*CLS/4; j += GT) {
            int p = j / 5;
            int g = j - p*5;              // float4 group within row
            float4 a0 = reinterpret_cast<const float4*>(att0)[p];
            float4 a1 = reinterpret_cast<const float4*>(att1)[p];
            const float4* zi = zin4 + p*5 + g;
            float4 s0 = zi[0];
            float4 s1 = zi[5];
            float4 s2 = zi[10];
            float4 s3 = zi[15];
            float4 s4 = zi[20];
            float4 s5 = zi[25];
            float4 s6 = zi[30];
            float4 acc;
            acc.x = a0.x*s0.x; acc.y = a0.x*s0.y; acc.z = a0.x*s0.z; acc.w = a0.x*s0.w;
            acc.x = fmaf(a0.y, s1.x, acc.x); acc.y = fmaf(a0.y, s1.y, acc.y);
            acc.z = fmaf(a0.y, s1.z, acc.z); acc.w = fmaf(a0.y, s1.w, acc.w);
            acc.x = fmaf(a0.z, s2.x, acc.x); acc.y = fmaf(a0.z, s2.y, acc.y);
            acc.z = fmaf(a0.z, s2.z, acc.z); acc.w = fmaf(a0.z, s2.w, acc.w);
            acc.x = fmaf(a0.w, s3.x, acc.x); acc.y = fmaf(a0.w, s3.y, acc.y);
            acc.z = fmaf(a0.w, s3.z, acc.z); acc.w = fmaf(a0.w, s3.w, acc.w);
            acc.x = fmaf(a1.x, s4.x, acc.x); acc.y = fmaf(a1.x, s4.y, acc.y);
            acc.z = fmaf(a1.x, s4.z, acc.z); acc.w = fmaf(a1.x, s4.w, acc.w);
            acc.x = fmaf(a1.y, s5.x, acc.x); acc.y = fmaf(a1.y, s5.y, acc.y);
            acc.z = fmaf(a1.y, s5.z, acc.z); acc.w = fmaf(a1.y, s5.w, acc.w);
            acc.x = fmaf(a1.z, s6.x, acc.x); acc.y = fmaf(a1.z, s6.y, acc.y);
            acc.z = fmaf(a1.z, s6.z, acc.z); acc.w = fmaf(a1.z, s6.w, acc.w);
            float4 z0v = reinterpret_cast<const float4*>(zA)[(p+3)*5 + g];
            float4 v;
            v.x = fmaf(1.f - ALPHA, acc.x, ALPHA*z0v.x);
            v.y = fmaf(1.f - ALPHA, acc.y, ALPHA*z0v.y);
            v.z = fmaf(1.f - ALPHA, acc.z, ALPHA*z0v.z);
            v.w = fmaf(1.f - ALPHA, acc.w, ALPHA*z0v.w);
            if (hop == KHOPS-1) {
                float* o = dsb + p*CLS + g*4;
                float ex0 = (v.x > 0.f) ? v.x : expm1f(v.x);
                float ex1 = (v.y > 0.f) ? v.y : expm1f(v.y);
                float ex2 = (v.z > 0.f) ? v.z : expm1f(v.z);
                float ex3 = (v.w > 0.f) ? v.w : expm1f(v.w);
                atomicAdd(o+0, ex0 * (1.f/HEADS));
                atomicAdd(o+1, ex1 * (1.f/HEADS));
                atomicAdd(o+2, ex2 * (1.f/HEADS));
                atomicAdd(o+3, ex3 * (1.f/HEADS));
            } else {
                zout4[(p+3)*5 + g] = v;
            }
        }
        if (hop < KHOPS-1) __syncthreads();
    }
}

// ---------------- K4: gated readout ----------------
__global__ __launch_bounds__(256) void k_readout(
    const float* __restrict__ w_gate, const float* __restrict__ b_gate,
    float* __restrict__ out)
{
    __shared__ float wg[CLS];
    __shared__ float sred[240];
    const int t = threadIdx.x;
    if (t < CLS) wg[t] = w_gate[t];
    __syncthreads();
    const int doc = blockIdx.x;
    const float bg = b_gate[0];
    float acc = 0.f;
    if (t < 240) {
        int c = t % CLS, r = t / CLS;
        for (int p = r; p < LSEQ; p += 12) {
            const float* hr = g_h + (doc*LSEQ + p)*CLS;
            float dot = bg;
            #pragma unroll
            for (int k = 0; k < CLS; k++) dot = fmaf(hr[k], wg[k], dot);
            float gate = 1.f / (1.f + expf(-dot));
            acc = fmaf(gate, hr[c], acc);
        }
        sred[t] = acc;
    }
    __syncthreads();
    if (t < CLS) {
        float s = 0.f;
        #pragma unroll
        for (int r = 0; r < 12; r++) s += sred[r*CLS + t];
        out[doc*CLS + t] = s;
    }
}

// ---------------- launch ----------------
extern "C" void kernel_launch(void* const* d_in, const int* in_sizes, int n_in,
                              void* d_out, int out_size)
{
    const int*   node_ids = (const int*)  d_in[0];
    const float* emb    = (const float*) d_in[4];
    const float* W1     = (const float*) d_in[5];
    const float* b1     = (const float*) d_in[6];
    const float* W2     = (const float*) d_in[7];
    const float* b2     = (const float*) d_in[8];
    const float* gat_W  = (const float*) d_in[9];
    const float* a_src  = (const float*) d_in[10];
    const float* a_dst  = (const float*) d_in[11];
    const float* w_gate = (const float*) d_in[12];
    const float* b_gate = (const float*) d_in[13];
    float* out = (float*)d_out;

    cudaFuncSetAttribute(k_gemm1tc,
        cudaFuncAttributeMaxDynamicSharedMemorySize, GEMM_SMEM);
    cudaFuncSetAttribute(k_gat,
        cudaFuncAttributeMaxDynamicSharedMemorySize, GAT_SMEM);

    k_prepw<<<DIM, 256>>>(W1);                                           // 768
    k_gemm1tc<<<NNODES/TM, 256, GEMM_SMEM>>>(node_ids, emb, b1, W2, b2); // 280
    for (int l = 0; l < LAYERS; l++) {
        if (l > 0) k_zero<<<NNODES*CLS/1024, 256>>>(0);                  // zero g_h
        k_gat<<<B_DOCS*HEADS, GT, GAT_SMEM>>>(gat_W, a_src, a_dst, l);   // 1024
    }
    k_readout<<<B_DOCS, 256>>>(w_gate, b_gate, out);
}

// round 14
// speedup vs baseline: 1.1045x; 1.0064x over previous
#include <cuda_runtime.h>
#include <cuda_fp16.h>
#include <math.h>
#include <stdint.h>

// ---------------- problem constants ----------------
#define VOCAB   50000
#define B_DOCS  128
#define LSEQ    350
#define NGW     3
#define DIM     768
#define HID     256
#define CLS     20
#define HEADS   8
#define LAYERS  2
#define KHOPS   3
#define ALPHA   0.15f
#define NNODES  (B_DOCS*LSEQ)      // 44800
#define WIN     7

// ---------------- scratch ----------------
__device__ float g_h [NNODES*CLS];                 // node features (ping)
__device__ float g_hB[NNODES*CLS];                 // node features (pong)
__device__ __align__(1024) __half g_Wt[HID*DIM];   // W1^T fp16, pre-swizzled 16KB tiles

// ---------------- helpers ----------------
__device__ __forceinline__ uint32_t smem_u32(const void* p) {
    uint32_t a;
    asm("{ .reg .u64 t; cvta.to.shared.u64 t, %1; cvt.u32.u64 %0, t; }"
        : "=r"(a) : "l"(p));
    return a;
}
#define SWZ64(o) ((o) ^ (((o) >> 3) & 0x30))

__device__ __forceinline__ void ldsm4(uint32_t* r, uint32_t addr) {
    asm volatile("ldmatrix.sync.aligned.m8n8.x4.shared.b16 {%0,%1,%2,%3}, [%4];"
        : "=r"(r[0]), "=r"(r[1]), "=r"(r[2]), "=r"(r[3]) : "r"(addr));
}
__device__ __forceinline__ void mma16816(float* c, const uint32_t* a, const uint32_t* b) {
    asm volatile("mma.sync.aligned.m16n8k16.row.col.f32.f16.f16.f32 "
        "{%0,%1,%2,%3}, {%4,%5,%6,%7}, {%8,%9}, {%0,%1,%2,%3};"
        : "+f"(c[0]), "+f"(c[1]), "+f"(c[2]), "+f"(c[3])
        : "r"(a[0]), "r"(a[1]), "r"(a[2]), "r"(a[3]), "r"(b[0]), "r"(b[1]));
}
__device__ __forceinline__ void cpasync16(uint32_t dst, const void* src) {
    size_t gs = __cvta_generic_to_global(src);
    asm volatile("cp.async.cg.shared.global [%0], [%1], 16;"
                 :: "r"(dst), "l"(gs) : "memory");
}
#define CP_COMMIT() asm volatile("cp.async.commit_group;" ::: "memory")
#define CP_WAIT0()  asm volatile("cp.async.wait_group 0;" ::: "memory")
#define CP_WAIT1()  asm volatile("cp.async.wait_group 1;" ::: "memory")
#define CP_WAIT2()  asm volatile("cp.async.wait_group 2;" ::: "memory")
// TMA bulk copy gmem -> smem with mbarrier transaction accounting
__device__ __forceinline__ void bulk_g2s(uint32_t dst, const void* src,
                                         uint32_t bytes, uint32_t mbar) {
    size_t gs = __cvta_generic_to_global(src);
    asm volatile(
        "cp.async.bulk.shared::cluster.global.mbarrier::complete_tx::bytes "
        "[%0], [%1], %2, [%3];"
        :: "r"(dst), "l"(gs), "r"(bytes), "r"(mbar) : "memory");
}
#define MBAR_INIT(a,c) asm volatile("mbarrier.init.shared.b64 [%0], %1;" \
    :: "r"(a), "r"(c) : "memory")
#define MBAR_EXPECT(a,tx) asm volatile( \
    "mbarrier.arrive.expect_tx.shared.b64 _, [%0], %1;" \
    :: "r"(a), "r"(tx) : "memory")
#define MBAR_WAIT(addr, par) do { \
    asm volatile("{\n\t.reg .pred P1;\n\tWAIT_%=:\n\t" \
        "mbarrier.try_wait.parity.acquire.cta.shared::cta.b64 P1, [%0], %1;\n\t" \
        "@P1 bra.uni DONE_%=;\n\tbra.uni WAIT_%=;\n\tDONE_%=:\n\t}" \
        :: "r"(addr), "r"(par) : "memory"); } while (0)
#define FENCE_ASYNC() asm volatile("fence.proxy.async.shared::cta;" ::: "memory")

// ---------------- K0: W1 -> fp16 transposed, pre-swizzled SW64 16KB tiles
__global__ __launch_bounds__(256) void k_prepw(const float* __restrict__ W1)
{
    const int k = blockIdx.x;          // 0..767
    const int n = threadIdx.x;         // 0..255
    float v = W1[k*HID + n];
    int ch = k >> 5, kk = k & 31;
    uint32_t byte = SWZ64((uint32_t)(n*64 + kk*2));
    g_Wt[(((uint32_t)ch*16384) + byte) >> 1] = __float2half_rn(v);
}

// ---------------- K1: gather + GEMM1(fp16 mma) + GEMM2 fused -------------
// 3-stage pipeline; convert(ch+1) overlapped with compute(ch) (no barrier
// between them — each thread converts only the bytes it cp.async'd itself).
#define TM       160
#define KB       32
#define NCH      (DIM/KB)        // 24
#define OFF_ROWS 0
#define OFF_B1   768
#define OFF_B2   1792
#define OFF_MBAR 1920            // 3 x 8B mbarriers
#define OFF_AS   2048            // A fp16:   3 x 10240 -> 32768
#define OFF_AR   32768           // A raw:    3 x 20480 -> 94208
#define OFF_BB   94208           // B fp16:   3 x 16384 -> 143360
#define XS_STRIDE 259
#define OFF_XS   2048
#define OFF_W2S  167808
#define OFF_HRED 188288
#define GEMM_SMEM 213888

__device__ __forceinline__ uint32_t a_addr64(uint32_t base, int row0, int kb, int lane) {
    int q = lane >> 3, lr = lane & 7;
    int row = row0 + ((q & 1) << 3) + lr;
    int k   = kb + ((q >> 1) << 3);
    return base + SWZ64((uint32_t)(row*64 + k*2));
}
__device__ __forceinline__ uint32_t b_addr64(uint32_t base, int n0, int kb, int lane) {
    int q = lane >> 3, lr = lane & 7;
    int n = n0 + ((q >> 1) << 3) + lr;
    int k = kb + ((q & 1) << 3);
    return base + SWZ64((uint32_t)(n*64 + k*2));
}

__device__ __forceinline__ void issue_A(
    uint32_t sb, const float* __restrict__ emb, const int* rows_s, int ch, int t)
{
    const uint32_t adst = sb + OFF_AR + (uint32_t)(ch % 3)*20480;
    const int k0 = ch * KB;
    #pragma unroll
    for (int i = 0; i < 5; i++) {
        int idx = t + i*256;               // 1280 = 160m x 8c
        int m = idx >> 3, c = idx & 7;
        cpasync16(adst + (uint32_t)(m*128 + c*16),
                  emb + (size_t)rows_s[m]*DIM + k0 + c*4);
    }
}

__device__ __forceinline__ void convert_chunk(char* smc, int slot, int t)
{
    const char* raw = smc + OFF_AR + slot*20480;
    char* dH = smc + OFF_AS + slot*10240;
    #pragma unroll
    for (int i = 0; i < 5; i++) {
        int idx = t + i*256;
        int m = idx >> 3, g = idx & 7;
        float4 v = *reinterpret_cast<const float4*>(raw + m*128 + g*16);
        __half2 h0 = __float22half2_rn(make_float2(v.x, v.y));
        __half2 h1 = __float22half2_rn(make_float2(v.z, v.w));
        uint2 hv;
        hv.x = *reinterpret_cast<uint32_t*>(&h0);
        hv.y = *reinterpret_cast<uint32_t*>(&h1);
        *reinterpret_cast<uint2*>(dH + SWZ64((uint32_t)(m*64 + g*8))) = hv;
    }
}

__global__ __launch_bounds__(256, 1) void k_gemm1tc(
    const int* __restrict__ node_ids, const float* __restrict__ emb,
    const float* __restrict__ b1, const float* __restrict__ W2,
    const float* __restrict__ b2)
{
    extern __shared__ char smc[];
    const uint32_t sb = smem_u32(smc);
    const int t = threadIdx.x, lane = t & 31, wid = t >> 5;
    const int wm = wid >> 2, wn = wid & 3;       // 2 x 4 warps
    const int m0 = blockIdx.x * TM;
    int*   rows_s = (int*)(smc + OFF_ROWS);
    float* b1s    = (float*)(smc + OFF_B1);
    float* b2s    = (float*)(smc + OFF_B2);

    if (t < TM) rows_s[t] = node_ids[m0 + t];
    b1s[t] = b1[t];
    if (t < CLS) b2s[t] = b2[t];

    // zero this block's slice of g_hB (layer-0 accumulation target)
    {
        float4* zb = reinterpret_cast<float4*>(g_hB + (size_t)m0*CLS);
        #pragma unroll
        for (int i = t; i < TM*CLS/4; i += 256)
            zb[i] = make_float4(0.f, 0.f, 0.f, 0.f);
    }
    if (t == 0) {
        MBAR_INIT(sb + OFF_MBAR,      1);
        MBAR_INIT(sb + OFF_MBAR + 8,  1);
        MBAR_INIT(sb + OFF_MBAR + 16, 1);
    }
    __syncthreads();
    FENCE_ASYNC();
    if (t == 0) {
        MBAR_EXPECT(sb + OFF_MBAR,      16384);   // chunk 0
        MBAR_EXPECT(sb + OFF_MBAR + 8,  16384);   // chunk 1
        MBAR_EXPECT(sb + OFF_MBAR + 16, 16384);   // chunk 2
    }
    __syncthreads();

    // prologue: stage chunks 0,1,2
    issue_A(sb, emb, rows_s, 0, t); CP_COMMIT();
    issue_A(sb, emb, rows_s, 1, t); CP_COMMIT();
    issue_A(sb, emb, rows_s, 2, t); CP_COMMIT();
    if (t == 0) {
        bulk_g2s(sb + OFF_BB,         g_Wt,         16384, sb + OFF_MBAR);
        bulk_g2s(sb + OFF_BB + 16384, g_Wt + 8192,  16384, sb + OFF_MBAR + 8);
        bulk_g2s(sb + OFF_BB + 32768, g_Wt + 16384, 16384, sb + OFF_MBAR + 16);
    }
    CP_WAIT2();                 // chunk 0's A arrived (per-thread)
    convert_chunk(smc, 0, t);   // own bytes only
    __syncthreads();            // AS[0] visible to all

    float acc[5][8][4];
    #pragma unroll
    for (int mt = 0; mt < 5; mt++)
        #pragma unroll
        for (int nt = 0; nt < 8; nt++)
            #pragma unroll
            for (int q = 0; q < 4; q++) acc[mt][nt][q] = 0.f;

    for (int ch = 0; ch < NCH; ch++) {
        const int slot = ch % 3;
        // ---- convert next chunk (own cp.async bytes; overlaps compute) ----
        if (ch + 1 < NCH) {
            if (ch + 2 < NCH) CP_WAIT1(); else CP_WAIT0();
            convert_chunk(smc, (ch + 1) % 3, t);
        }
        // ---- compute chunk ch ----
        MBAR_WAIT(sb + OFF_MBAR + slot*8, (uint32_t)((ch / 3) & 1));
        const uint32_t aH = sb + OFF_AS + slot*10240;
        const uint32_t bH = sb + OFF_BB + slot*16384;
        #pragma unroll
        for (int ks = 0; ks < 2; ks++) {
            const int kb = ks*16;
            uint32_t af[5][4], bf[8][2];
            #pragma unroll
            for (int mt = 0; mt < 5; mt++)
                ldsm4(af[mt], a_addr64(aH, wm*80 + mt*16, kb, lane));
            #pragma unroll
            for (int p = 0; p < 4; p++) {
                uint32_t r[4];
                ldsm4(r, b_addr64(bH, wn*64 + p*16, kb, lane));
                bf[p*2][0]=r[0]; bf[p*2][1]=r[1];
                bf[p*2+1][0]=r[2]; bf[p*2+1][1]=r[3];
            }
            #pragma unroll
            for (int mt = 0; mt < 5; mt++)
                #pragma unroll
                for (int nt = 0; nt < 8; nt++)
                    mma16816(acc[mt][nt], af[mt], bf[nt]);
        }
        __syncthreads();        // AS[s1] visible; slot reads done
        if (ch + 3 < NCH) {     // refill this slot with ch+3
            issue_A(sb, emb, rows_s, ch + 3, t);
            CP_COMMIT();
            if (t == 0) {
                MBAR_EXPECT(sb + OFF_MBAR + slot*8, 16384);
                bulk_g2s(sb + OFF_BB + slot*16384, g_Wt + (ch + 3)*8192,
                         16384, sb + OFF_MBAR + slot*8);
            }
        }
    }
    __syncthreads();

    // ---- epilogue 1: acc -> XS with +b1, ReLU ----
    float* XS = (float*)(smc + OFF_XS);
    {
        const int lr4 = lane >> 2, lc2 = (lane & 3)*2;
        #pragma unroll
        for (int mt = 0; mt < 5; mt++) {
            #pragma unroll
            for (int nt = 0; nt < 8; nt++) {
                int r0 = wm*80 + mt*16 + lr4;
                int c0 = wn*64 + nt*8 + lc2;
                float ba = b1s[c0], bb = b1s[c0+1];
                XS[r0*XS_STRIDE + c0]       = fmaxf(acc[mt][nt][0] + ba, 0.f);
                XS[r0*XS_STRIDE + c0 + 1]   = fmaxf(acc[mt][nt][1] + bb, 0.f);
                XS[(r0+8)*XS_STRIDE + c0]   = fmaxf(acc[mt][nt][2] + ba, 0.f);
                XS[(r0+8)*XS_STRIDE + c0+1] = fmaxf(acc[mt][nt][3] + bb, 0.f);
            }
        }
    }
    float* W2S  = (float*)(smc + OFF_W2S);
    float* HRED = (float*)(smc + OFF_HRED);
    for (int i = t; i < HID*CLS; i += 256) W2S[i] = W2[i];
    __syncthreads();

    // ---- epilogue 2: h = relu(x) @ W2, (row, K-half) split over 320 workers
    for (int p = t; p < 2*TM; p += 256) {
        int half = p / TM, row = p - half*TM;
        float hacc[CLS];
        #pragma unroll
        for (int c = 0; c < CLS; c++) hacc[c] = 0.f;
        const float* xr = XS + row*XS_STRIDE + half*128;
        #pragma unroll 4
        for (int n = 0; n < 128; n++) {
            float xv = xr[n];
            const float4* w4 = reinterpret_cast<const float4*>(
                W2S + (half*128 + n)*CLS);
            #pragma unroll
            for (int q = 0; q < 5; q++) {
                float4 w = w4[q];
                hacc[q*4+0] = fmaf(xv, w.x, hacc[q*4+0]);
                hacc[q*4+1] = fmaf(xv, w.y, hacc[q*4+1]);
                hacc[q*4+2] = fmaf(xv, w.z, hacc[q*4+2]);
                hacc[q*4+3] = fmaf(xv, w.w, hacc[q*4+3]);
            }
        }
        #pragma unroll
        for (int c = 0; c < CLS; c++) HRED[p*CLS + c] = hacc[c];
    }
    __syncthreads();
    if (t < TM) {
        #pragma unroll
        for (int c = 0; c < CLS; c++)
            g_h[(m0 + t)*CLS + c] =
                HRED[t*CLS + c] + HRED[(TM + t)*CLS + c] + b2s[c];
    }
}

// ---------------- K2: zero a feature buffer ----------------
__global__ __launch_bounds__(256) void k_zero(int which)
{
    float* p = which ? g_hB : g_h;
    int i = blockIdx.x*256 + threadIdx.x;      // NNODES*CLS/4 = 224000
    reinterpret_cast<float4*>(p)[i] = make_float4(0.f, 0.f, 0.f, 0.f);
}

// ---------------- K3: fused GAT layer (R10-proven flat hop) --------------
#define GT 512
#define ZROWS 356
#define ZFL   (ZROWS*CLS)        // 7120 floats per buffer
#define OFF_zA 0
#define OFF_zB ZFL               // 7120
#define OFF_zC (2*ZFL)           // 14240
#define OFF_A0 (3*ZFL)           // 21360  (350 float4)
#define OFF_A1 (OFF_A0 + 1400)   // 22760
#define OFF_ES (OFF_A1 + 1400)   // 24160
#define OFF_ED (OFF_ES + 352)    // 24512
#define OFF_WB (OFF_ED + 352)    // 24864
#define OFF_AS2 (OFF_WB + 400)   // 25264
#define OFF_AD2 (OFF_AS2 + 20)   // 25284
#define GAT_FLOATS (OFF_AD2 + 28) // 25312
#define GAT_SMEM (GAT_FLOATS*4)   // 101248 bytes
__global__ __launch_bounds__(GT, 2) void k_gat(
    const float* __restrict__ gat_W, const float* __restrict__ a_src,
    const float* __restrict__ a_dst, int layer)
{
    extern __shared__ float gs[];
    float* zA   = gs + OFF_zA;   // z0, persists all hops
    float* zB   = gs + OFF_zB;   // h on load, then hop-0 out
    float* zC   = gs + OFF_zC;   // hop-1 out
    float* att0 = gs + OFF_A0;
    float* att1 = gs + OFF_A1;
    float* esb  = gs + OFF_ES;
    float* edb  = gs + OFF_ED;
    float* Wb   = gs + OFF_WB;
    float* asb  = gs + OFF_AS2;
    float* adb  = gs + OFF_AD2;
    const int t = threadIdx.x;
    const int hd = blockIdx.x & 7, doc = blockIdx.x >> 3;
    const float* src = (layer == 0) ? g_h : g_hB;
    float*       dst = (layer == 0) ? g_hB : g_h;

    // load h straight into zB rows 3..352 (float4 copy, no transpose)
    const float4* hg = reinterpret_cast<const float4*>(src + (size_t)doc*LSEQ*CLS);
    float4* zB4 = reinterpret_cast<float4*>(zB);
    for (int i = t; i < LSEQ*CLS/4; i += GT) zB4[i + 15] = hg[i];
    const float* Wg = gat_W + ((size_t)layer*HEADS + hd)*CLS*CLS;
    for (int i = t; i < CLS*CLS; i += GT) Wb[i] = Wg[i];
    if (t >= GT-32 && t < GT-32+CLS) {
        int c = t - (GT-32);
        asb[c] = a_src[(layer*HEADS + hd)*CLS + c];
        adb[c] = a_dst[(layer*HEADS + hd)*CLS + c];
    }
    // zero halos (rows -3..-1 and 350..352) of all three buffers
    if (t >= GT-128 && t < GT-128+90) {
        int r0 = t - (GT-128);
        int buf = r0 / 30, r = r0 % 30;
        float4* z = reinterpret_cast<float4*>(gs + buf*ZFL);
        int idx = (r < 15) ? r : (ZFL/4 - 30 + r);
        z[idx] = make_float4(0.f, 0.f, 0.f, 0.f);
    }
    __syncthreads();

    // projection: zA[p+3][c] = sum_c2 h[p][c2] * W[c2][c]; es/ed scores
    for (int p = t; p < LSEQ; p += GT) {
        const float4* hr4 = reinterpret_cast<const float4*>(zB + (p+3)*CLS);
        float hv[CLS];
        #pragma unroll
        for (int q = 0; q < 5; q++) {
            float4 v = hr4[q];
            hv[q*4+0] = v.x; hv[q*4+1] = v.y; hv[q*4+2] = v.z; hv[q*4+3] = v.w;
        }
        float zr[CLS];
        #pragma unroll
        for (int c = 0; c < CLS; c++) zr[c] = 0.f;
        #pragma unroll
        for (int c2 = 0; c2 < CLS; c2++) {
            #pragma unroll
            for (int c = 0; c < CLS; c++)
                zr[c] = fmaf(hv[c2], Wb[c2*CLS + c], zr[c]);
        }
        float es = 0.f, ed = 0.f;
        #pragma unroll
        for (int c = 0; c < CLS; c++) {
            es = fmaf(zr[c], asb[c], es);
            ed = fmaf(zr[c], adb[c], ed);
        }
        esb[p] = es; edb[p] = ed;
        float4* za4 = reinterpret_cast<float4*>(zA + (p+3)*CLS);
        #pragma unroll
        for (int q = 0; q < 5; q++)
            za4[q] = make_float4(zr[q*4+0], zr[q*4+1], zr[q*4+2], zr[q*4+3]);
    }
    __syncthreads();

    // banded softmax -> att planes (float4 rows)
    for (int p = t; p < LSEQ; p += GT) {
        float ed = edb[p];
        float e[WIN], m = -1e30f;
        #pragma unroll
        for (int w = 0; w < WIN; w++) {
            int j = p - NGW + w;
            bool valid = (j >= 0) & (j < LSEQ);
            int jj = valid ? j : p;
            float ev = esb[jj] + ed;
            ev = ev > 0.f ? ev : 0.2f*ev;
            e[w] = valid ? ev : -1e30f;
            m = fmaxf(m, e[w]);
        }
        float ex[WIN], s = 0.f;
        #pragma unroll
        for (int w = 0; w < WIN; w++) {
            ex[w] = (e[w] > -1e29f) ? expf(e[w] - m) : 0.f;
            s += ex[w];
        }
        float inv = 1.f / (s + 1e-9f);
        reinterpret_cast<float4*>(att0)[p] =
            make_float4(ex[0]*inv, ex[1]*inv, ex[2]*inv, ex[3]*inv);
        reinterpret_cast<float4*>(att1)[p] =
            make_float4(ex[4]*inv, ex[5]*inv, ex[6]*inv, 0.f);
    }
    __syncthreads();

    // hops: zA -> zB -> zC -> gmem atomics; all accesses float4
    float* dsb = dst + (size_t)doc*LSEQ*CLS;
    #pragma unroll
    for (int hop = 0; hop < KHOPS; hop++) {
        const float4* zin4  = reinterpret_cast<const float4*>(
            (hop == 0) ? zA : ((hop == 1) ? zB : zC));
        float4* zout4 = reinterpret_cast<float4*>((hop == 0) ? zB : zC);
        for (int j = t; j < LSEQ*CLS/4; j += GT) {
            int p = j / 5;
            int g = j - p*5;              // float4 group within row
            float4 a0 = reinterpret_cast<const float4*>(att0)[p];
            float4 a1 = reinterpret_cast<const float4*>(att1)[p];
            const float4* zi = zin4 + p*5 + g;
            float4 s0 = zi[0];
            float4 s1 = zi[5];
            float4 s2 = zi[10];
            float4 s3 = zi[15];
            float4 s4 = zi[20];
            float4 s5 = zi[25];
            float4 s6 = zi[30];
            float4 acc;
            acc.x = a0.x*s0.x; acc.y = a0.x*s0.y; acc.z = a0.x*s0.z; acc.w = a0.x*s0.w;
            acc.x = fmaf(a0.y, s1.x, acc.x); acc.y = fmaf(a0.y, s1.y, acc.y);
            acc.z = fmaf(a0.y, s1.z, acc.z); acc.w = fmaf(a0.y, s1.w, acc.w);
            acc.x = fmaf(a0.z, s2.x, acc.x); acc.y = fmaf(a0.z, s2.y, acc.y);
            acc.z = fmaf(a0.z, s2.z, acc.z); acc.w = fmaf(a0.z, s2.w, acc.w);
            acc.x = fmaf(a0.w, s3.x, acc.x); acc.y = fmaf(a0.w, s3.y, acc.y);
            acc.z = fmaf(a0.w, s3.z, acc.z); acc.w = fmaf(a0.w, s3.w, acc.w);
            acc.x = fmaf(a1.x, s4.x, acc.x); acc.y = fmaf(a1.x, s4.y, acc.y);
            acc.z = fmaf(a1.x, s4.z, acc.z); acc.w = fmaf(a1.x, s4.w, acc.w);
            acc.x = fmaf(a1.y, s5.x, acc.x); acc.y = fmaf(a1.y, s5.y, acc.y);
            acc.z = fmaf(a1.y, s5.z, acc.z); acc.w = fmaf(a1.y, s5.w, acc.w);
            acc.x = fmaf(a1.z, s6.x, acc.x); acc.y = fmaf(a1.z, s6.y, acc.y);
            acc.z = fmaf(a1.z, s6.z, acc.z); acc.w = fmaf(a1.z, s6.w, acc.w);
            float4 z0v = reinterpret_cast<const float4*>(zA)[(p+3)*5 + g];
            float4 v;
            v.x = fmaf(1.f - ALPHA, acc.x, ALPHA*z0v.x);
            v.y = fmaf(1.f - ALPHA, acc.y, ALPHA*z0v.y);
            v.z = fmaf(1.f - ALPHA, acc.z, ALPHA*z0v.z);
            v.w = fmaf(1.f - ALPHA, acc.w, ALPHA*z0v.w);
            if (hop == KHOPS-1) {
                float* o = dsb + p*CLS + g*4;
                float ex0 = (v.x > 0.f) ? v.x : expm1f(v.x);
                float ex1 = (v.y > 0.f) ? v.y : expm1f(v.y);
                float ex2 = (v.z > 0.f) ? v.z : expm1f(v.z);
                float ex3 = (v.w > 0.f) ? v.w : expm1f(v.w);
                atomicAdd(o+0, ex0 * (1.f/HEADS));
                atomicAdd(o+1, ex1 * (1.f/HEADS));
                atomicAdd(o+2, ex2 * (1.f/HEADS));
                atomicAdd(o+3, ex3 * (1.f/HEADS));
            } else {
                zout4[(p+3)*5 + g] = v;
            }
        }
        if (hop < KHOPS-1) __syncthreads();
    }
}

// ---------------- K4: gated readout ----------------
__global__ __launch_bounds__(256) void k_readout(
    const float* __restrict__ w_gate, const float* __restrict__ b_gate,
    float* __restrict__ out)
{
    __shared__ float wg[CLS];
    __shared__ float sred[240];
    const int t = threadIdx.x;
    if (t < CLS) wg[t] = w_gate[t];
    __syncthreads();
    const int doc = blockIdx.x;
    const float bg = b_gate[0];
    float acc = 0.f;
    if (t < 240) {
        int c = t % CLS, r = t / CLS;
        for (int p = r; p < LSEQ; p += 12) {
            const float* hr = g_h + (doc*LSEQ + p)*CLS;
            float dot = bg;
            #pragma unroll
            for (int k = 0; k < CLS; k++) dot = fmaf(hr[k], wg[k], dot);
            float gate = 1.f / (1.f + expf(-dot));
            acc = fmaf(gate, hr[c], acc);
        }
        sred[t] = acc;
    }
    __syncthreads();
    if (t < CLS) {
        float s = 0.f;
        #pragma unroll
        for (int r = 0; r < 12; r++) s += sred[r*CLS + t];
        out[doc*CLS + t] = s;
    }
}

// ---------------- launch ----------------
extern "C" void kernel_launch(void* const* d_in, const int* in_sizes, int n_in,
                              void* d_out, int out_size)
{
    const int*   node_ids = (const int*)  d_in[0];
    const float* emb    = (const float*) d_in[4];
    const float* W1     = (const float*) d_in[5];
    const float* b1     = (const float*) d_in[6];
    const float* W2     = (const float*) d_in[7];
    const float* b2     = (const float*) d_in[8];
    const float* gat_W  = (const float*) d_in[9];
    const float* a_src  = (const float*) d_in[10];
    const float* a_dst  = (const float*) d_in[11];
    const float* w_gate = (const float*) d_in[12];
    const float* b_gate = (const float*) d_in[13];
    float* out = (float*)d_out;

    cudaFuncSetAttribute(k_gemm1tc,
        cudaFuncAttributeMaxDynamicSharedMemorySize, GEMM_SMEM);
    cudaFuncSetAttribute(k_gat,
        cudaFuncAttributeMaxDynamicSharedMemorySize, GAT_SMEM);

    k_prepw<<<DIM, 256>>>(W1);                                           // 768
    k_gemm1tc<<<NNODES/TM, 256, GEMM_SMEM>>>(node_ids, emb, b1, W2, b2); // 280
    for (int l = 0; l < LAYERS; l++) {
        if (l > 0) k_zero<<<NNODES*CLS/1024, 256>>>(0);                  // zero g_h
        k_gat<<<B_DOCS*HEADS, GT, GAT_SMEM>>>(gat_W, a_src, a_dst, l);   // 1024
    }
    k_readout<<<B_DOCS, 256>>>(w_gate, b_gate, out);
}

// round 15
// speedup vs baseline: 1.1836x; 1.0716x over previous
#include <cuda_runtime.h>
#include <cuda_fp16.h>
#include <math.h>
#include <stdint.h>

// ---------------- problem constants ----------------
#define VOCAB   50000
#define B_DOCS  128
#define LSEQ    350
#define NGW     3
#define DIM     768
#define HID     256
#define CLS     20
#define HEADS   8
#define LAYERS  2
#define KHOPS   3
#define ALPHA   0.15f
#define NNODES  (B_DOCS*LSEQ)      // 44800
#define WIN     7

// ---------------- scratch ----------------
__device__ float g_h [NNODES*CLS];                 // node features (ping)
__device__ float g_hB[NNODES*CLS];                 // node features (pong)
__device__ __align__(1024) __half g_Wt[HID*DIM];   // W1^T fp16, pre-swizzled 16KB tiles

// ---------------- helpers ----------------
__device__ __forceinline__ uint32_t smem_u32(const void* p) {
    uint32_t a;
    asm("{ .reg .u64 t; cvta.to.shared.u64 t, %1; cvt.u32.u64 %0, t; }"
        : "=r"(a) : "l"(p));
    return a;
}
#define SWZ64(o) ((o) ^ (((o) >> 3) & 0x30))

__device__ __forceinline__ void ldsm4(uint32_t* r, uint32_t addr) {
    asm volatile("ldmatrix.sync.aligned.m8n8.x4.shared.b16 {%0,%1,%2,%3}, [%4];"
        : "=r"(r[0]), "=r"(r[1]), "=r"(r[2]), "=r"(r[3]) : "r"(addr));
}
__device__ __forceinline__ void mma16816(float* c, const uint32_t* a, const uint32_t* b) {
    asm volatile("mma.sync.aligned.m16n8k16.row.col.f32.f16.f16.f32 "
        "{%0,%1,%2,%3}, {%4,%5,%6,%7}, {%8,%9}, {%0,%1,%2,%3};"
        : "+f"(c[0]), "+f"(c[1]), "+f"(c[2]), "+f"(c[3])
        : "r"(a[0]), "r"(a[1]), "r"(a[2]), "r"(a[3]), "r"(b[0]), "r"(b[1]));
}
__device__ __forceinline__ void cpasync16(uint32_t dst, const void* src) {
    size_t gs = __cvta_generic_to_global(src);
    asm volatile("cp.async.cg.shared.global [%0], [%1], 16;"
                 :: "r"(dst), "l"(gs) : "memory");
}
#define CP_COMMIT() asm volatile("cp.async.commit_group;" ::: "memory")
#define CP_WAIT0()  asm volatile("cp.async.wait_group 0;" ::: "memory")
#define CP_WAIT1()  asm volatile("cp.async.wait_group 1;" ::: "memory")
#define CP_WAIT2()  asm volatile("cp.async.wait_group 2;" ::: "memory")
__device__ __forceinline__ void bulk_g2s(uint32_t dst, const void* src,
                                         uint32_t bytes, uint32_t mbar) {
    size_t gs = __cvta_generic_to_global(src);
    asm volatile(
        "cp.async.bulk.shared::cluster.global.mbarrier::complete_tx::bytes "
        "[%0], [%1], %2, [%3];"
        :: "r"(dst), "l"(gs), "r"(bytes), "r"(mbar) : "memory");
}
#define MBAR_INIT(a,c) asm volatile("mbarrier.init.shared.b64 [%0], %1;" \
    :: "r"(a), "r"(c) : "memory")
#define MBAR_EXPECT(a,tx) asm volatile( \
    "mbarrier.arrive.expect_tx.shared.b64 _, [%0], %1;" \
    :: "r"(a), "r"(tx) : "memory")
#define MBAR_WAIT(addr, par) do { \
    asm volatile("{\n\t.reg .pred P1;\n\tWAIT_%=:\n\t" \
        "mbarrier.try_wait.parity.acquire.cta.shared::cta.b64 P1, [%0], %1;\n\t" \
        "@P1 bra.uni DONE_%=;\n\tbra.uni WAIT_%=;\n\tDONE_%=:\n\t}" \
        :: "r"(addr), "r"(par) : "memory"); } while (0)
#define FENCE_ASYNC() asm volatile("fence.proxy.async.shared::cta;" ::: "memory")

// ---------------- K0: W1 -> fp16 transposed, pre-swizzled SW64 16KB tiles
__global__ __launch_bounds__(256) void k_prepw(const float* __restrict__ W1)
{
    const int k = blockIdx.x;          // 0..767
    const int n = threadIdx.x;         // 0..255
    float v = W1[k*HID + n];
    int ch = k >> 5, kk = k & 31;
    uint32_t byte = SWZ64((uint32_t)(n*64 + kk*2));
    g_Wt[(((uint32_t)ch*16384) + byte) >> 1] = __float2half_rn(v);
}

// ---------------- K1: gather + GEMM1(fp16 mma) + GEMM2 fused (R14) -------
#define TM       160
#define KB       32
#define NCH      (DIM/KB)        // 24
#define OFF_ROWS 0
#define OFF_B1   768
#define OFF_B2   1792
#define OFF_MBAR 1920            // 3 x 8B mbarriers
#define OFF_AS   2048            // A fp16:   3 x 10240 -> 32768
#define OFF_AR   32768           // A raw:    3 x 20480 -> 94208
#define OFF_BB   94208           // B fp16:   3 x 16384 -> 143360
#define XS_STRIDE 259
#define OFF_XS   2048
#define OFF_W2S  167808
#define OFF_HRED 188288
#define GEMM_SMEM 213888

__device__ __forceinline__ uint32_t a_addr64(uint32_t base, int row0, int kb, int lane) {
    int q = lane >> 3, lr = lane & 7;
    int row = row0 + ((q & 1) << 3) + lr;
    int k   = kb + ((q >> 1) << 3);
    return base + SWZ64((uint32_t)(row*64 + k*2));
}
__device__ __forceinline__ uint32_t b_addr64(uint32_t base, int n0, int kb, int lane) {
    int q = lane >> 3, lr = lane & 7;
    int n = n0 + ((q >> 1) << 3) + lr;
    int k = kb + ((q & 1) << 3);
    return base + SWZ64((uint32_t)(n*64 + k*2));
}

__device__ __forceinline__ void issue_A(
    uint32_t sb, const float* __restrict__ emb, const int* rows_s, int ch, int t)
{
    const uint32_t adst = sb + OFF_AR + (uint32_t)(ch % 3)*20480;
    const int k0 = ch * KB;
    #pragma unroll
    for (int i = 0; i < 5; i++) {
        int idx = t + i*256;               // 1280 = 160m x 8c
        int m = idx >> 3, c = idx & 7;
        cpasync16(adst + (uint32_t)(m*128 + c*16),
                  emb + (size_t)rows_s[m]*DIM + k0 + c*4);
    }
}

__device__ __forceinline__ void convert_chunk(char* smc, int slot, int t)
{
    const char* raw = smc + OFF_AR + slot*20480;
    char* dH = smc + OFF_AS + slot*10240;
    #pragma unroll
    for (int i = 0; i < 5; i++) {
        int idx = t + i*256;
        int m = idx >> 3, g = idx & 7;
        float4 v = *reinterpret_cast<const float4*>(raw + m*128 + g*16);
        __half2 h0 = __float22half2_rn(make_float2(v.x, v.y));
        __half2 h1 = __float22half2_rn(make_float2(v.z, v.w));
        uint2 hv;
        hv.x = *reinterpret_cast<uint32_t*>(&h0);
        hv.y = *reinterpret_cast<uint32_t*>(&h1);
        *reinterpret_cast<uint2*>(dH + SWZ64((uint32_t)(m*64 + g*8))) = hv;
    }
}

__global__ __launch_bounds__(256, 1) void k_gemm1tc(
    const int* __restrict__ node_ids, const float* __restrict__ emb,
    const float* __restrict__ b1, const float* __restrict__ W2,
    const float* __restrict__ b2)
{
    extern __shared__ char smc[];
    const uint32_t sb = smem_u32(smc);
    const int t = threadIdx.x, lane = t & 31, wid = t >> 5;
    const int wm = wid >> 2, wn = wid & 3;       // 2 x 4 warps
    const int m0 = blockIdx.x * TM;
    int*   rows_s = (int*)(smc + OFF_ROWS);
    float* b1s    = (float*)(smc + OFF_B1);
    float* b2s    = (float*)(smc + OFF_B2);

    if (t < TM) rows_s[t] = node_ids[m0 + t];
    b1s[t] = b1[t];
    if (t < CLS) b2s[t] = b2[t];

    {
        float4* zb = reinterpret_cast<float4*>(g_hB + (size_t)m0*CLS);
        #pragma unroll
        for (int i = t; i < TM*CLS/4; i += 256)
            zb[i] = make_float4(0.f, 0.f, 0.f, 0.f);
    }
    if (t == 0) {
        MBAR_INIT(sb + OFF_MBAR,      1);
        MBAR_INIT(sb + OFF_MBAR + 8,  1);
        MBAR_INIT(sb + OFF_MBAR + 16, 1);
    }
    __syncthreads();
    FENCE_ASYNC();
    if (t == 0) {
        MBAR_EXPECT(sb + OFF_MBAR,      16384);
        MBAR_EXPECT(sb + OFF_MBAR + 8,  16384);
        MBAR_EXPECT(sb + OFF_MBAR + 16, 16384);
    }
    __syncthreads();

    issue_A(sb, emb, rows_s, 0, t); CP_COMMIT();
    issue_A(sb, emb, rows_s, 1, t); CP_COMMIT();
    issue_A(sb, emb, rows_s, 2, t); CP_COMMIT();
    if (t == 0) {
        bulk_g2s(sb + OFF_BB,         g_Wt,         16384, sb + OFF_MBAR);
        bulk_g2s(sb + OFF_BB + 16384, g_Wt + 8192,  16384, sb + OFF_MBAR + 8);
        bulk_g2s(sb + OFF_BB + 32768, g_Wt + 16384, 16384, sb + OFF_MBAR + 16);
    }
    CP_WAIT2();
    convert_chunk(smc, 0, t);
    __syncthreads();

    float acc[5][8][4];
    #pragma unroll
    for (int mt = 0; mt < 5; mt++)
        #pragma unroll
        for (int nt = 0; nt < 8; nt++)
            #pragma unroll
            for (int q = 0; q < 4; q++) acc[mt][nt][q] = 0.f;

    for (int ch = 0; ch < NCH; ch++) {
        const int slot = ch % 3;
        if (ch + 1 < NCH) {
            if (ch + 2 < NCH) CP_WAIT1(); else CP_WAIT0();
            convert_chunk(smc, (ch + 1) % 3, t);
        }
        MBAR_WAIT(sb + OFF_MBAR + slot*8, (uint32_t)((ch / 3) & 1));
        const uint32_t aH = sb + OFF_AS + slot*10240;
        const uint32_t bH = sb + OFF_BB + slot*16384;
        #pragma unroll
        for (int ks = 0; ks < 2; ks++) {
            const int kb = ks*16;
            uint32_t af[5][4], bf[8][2];
            #pragma unroll
            for (int mt = 0; mt < 5; mt++)
                ldsm4(af[mt], a_addr64(aH, wm*80 + mt*16, kb, lane));
            #pragma unroll
            for (int p = 0; p < 4; p++) {
                uint32_t r[4];
                ldsm4(r, b_addr64(bH, wn*64 + p*16, kb, lane));
                bf[p*2][0]=r[0]; bf[p*2][1]=r[1];
                bf[p*2+1][0]=r[2]; bf[p*2+1][1]=r[3];
            }
            #pragma unroll
            for (int mt = 0; mt < 5; mt++)
                #pragma unroll
                for (int nt = 0; nt < 8; nt++)
                    mma16816(acc[mt][nt], af[mt], bf[nt]);
        }
        __syncthreads();
        if (ch + 3 < NCH) {
            issue_A(sb, emb, rows_s, ch + 3, t);
            CP_COMMIT();
            if (t == 0) {
                MBAR_EXPECT(sb + OFF_MBAR + slot*8, 16384);
                bulk_g2s(sb + OFF_BB + slot*16384, g_Wt + (ch + 3)*8192,
                         16384, sb + OFF_MBAR + slot*8);
            }
        }
    }
    __syncthreads();

    float* XS = (float*)(smc + OFF_XS);
    {
        const int lr4 = lane >> 2, lc2 = (lane & 3)*2;
        #pragma unroll
        for (int mt = 0; mt < 5; mt++) {
            #pragma unroll
            for (int nt = 0; nt < 8; nt++) {
                int r0 = wm*80 + mt*16 + lr4;
                int c0 = wn*64 + nt*8 + lc2;
                float ba = b1s[c0], bb = b1s[c0+1];
                XS[r0*XS_STRIDE + c0]       = fmaxf(acc[mt][nt][0] + ba, 0.f);
                XS[r0*XS_STRIDE + c0 + 1]   = fmaxf(acc[mt][nt][1] + bb, 0.f);
                XS[(r0+8)*XS_STRIDE + c0]   = fmaxf(acc[mt][nt][2] + ba, 0.f);
                XS[(r0+8)*XS_STRIDE + c0+1] = fmaxf(acc[mt][nt][3] + bb, 0.f);
            }
        }
    }
    float* W2S  = (float*)(smc + OFF_W2S);
    float* HRED = (float*)(smc + OFF_HRED);
    for (int i = t; i < HID*CLS; i += 256) W2S[i] = W2[i];
    __syncthreads();

    for (int p = t; p < 2*TM; p += 256) {
        int half = p / TM, row = p - half*TM;
        float hacc[CLS];
        #pragma unroll
        for (int c = 0; c < CLS; c++) hacc[c] = 0.f;
        const float* xr = XS + row*XS_STRIDE + half*128;
        #pragma unroll 4
        for (int n = 0; n < 128; n++) {
            float xv = xr[n];
            const float4* w4 = reinterpret_cast<const float4*>(
                W2S + (half*128 + n)*CLS);
            #pragma unroll
            for (int q = 0; q < 5; q++) {
                float4 w = w4[q];
                hacc[q*4+0] = fmaf(xv, w.x, hacc[q*4+0]);
                hacc[q*4+1] = fmaf(xv, w.y, hacc[q*4+1]);
                hacc[q*4+2] = fmaf(xv, w.z, hacc[q*4+2]);
                hacc[q*4+3] = fmaf(xv, w.w, hacc[q*4+3]);
            }
        }
        #pragma unroll
        for (int c = 0; c < CLS; c++) HRED[p*CLS + c] = hacc[c];
    }
    __syncthreads();
    if (t < TM) {
        #pragma unroll
        for (int c = 0; c < CLS; c++)
            g_h[(m0 + t)*CLS + c] =
                HRED[t*CLS + c] + HRED[(TM + t)*CLS + c] + b2s[c];
    }
}

// ---------------- K2: zero a feature buffer ----------------
__global__ __launch_bounds__(256) void k_zero(int which)
{
    float* p = which ? g_hB : g_h;
    int i = blockIdx.x*256 + threadIdx.x;
    reinterpret_cast<float4*>(p)[i] = make_float4(0.f, 0.f, 0.f, 0.f);
}

// ---------------- K3: fused GAT layer, fp16 z buffers, 3 CTA/SM ----------
// z buffers: 356 rows x 20 halves (rows -3..352), row = 40B.
// Unit of access: uint2 = 4 channels (group g); row = 5 groups.
#define GT 512
#define ZROWS 356
#define ZH    (ZROWS*CLS)          // 7120 halves per buffer
#define GAT_SMEM 58624
__global__ __launch_bounds__(GT, 3) void k_gat(
    const float* __restrict__ gat_W, const float* __restrict__ a_src,
    const float* __restrict__ a_dst, int layer)
{
    extern __shared__ char gsm[];
    __half* zA = (__half*)gsm;           // h, then z0 (persists)
    __half* zB = zA + ZH;
    __half* zC = zB + ZH;
    float* att0 = (float*)(gsm + 42720); // 1400
    float* att1 = att0 + 1400;           // 1400
    float* esb  = att1 + 1400;           // 352
    float* edb  = esb + 352;             // 352
    float* Wb   = edb + 352;             // 400
    float* asb  = Wb + 400;              // 20
    float* adb  = asb + 20;              // 20
    const int t = threadIdx.x;
    const int hd = blockIdx.x & 7, doc = blockIdx.x >> 3;
    const float* src = (layer == 0) ? g_h : g_hB;
    float*       dst = (layer == 0) ? g_hB : g_h;

    uint2* zA2 = reinterpret_cast<uint2*>(zA);
    uint2* zB2 = reinterpret_cast<uint2*>(zB);
    uint2* zC2 = reinterpret_cast<uint2*>(zC);

    // load h -> fp16 into zA rows 3..352
    const float4* hg = reinterpret_cast<const float4*>(src + (size_t)doc*LSEQ*CLS);
    for (int i = t; i < LSEQ*CLS/4; i += GT) {
        float4 v = hg[i];
        __half2 lo = __floats2half2_rn(v.x, v.y);
        __half2 hi = __floats2half2_rn(v.z, v.w);
        uint2 u;
        u.x = *reinterpret_cast<uint32_t*>(&lo);
        u.y = *reinterpret_cast<uint32_t*>(&hi);
        zA2[i + 15] = u;
    }
    const float* Wg = gat_W + ((size_t)layer*HEADS + hd)*CLS*CLS;
    for (int i = t; i < CLS*CLS; i += GT) Wb[i] = Wg[i];
    if (t >= GT-32 && t < GT-32+CLS) {
        int c = t - (GT-32);
        asb[c] = a_src[(layer*HEADS + hd)*CLS + c];
        adb[c] = a_dst[(layer*HEADS + hd)*CLS + c];
    }
    // zero halos (15 uint2 per end per buffer; 90 total)
    if (t >= GT-128 && t < GT-128+90) {
        int r0 = t - (GT-128);
        int buf = r0 / 30, r = r0 % 30;
        uint2* z = (buf == 0) ? zA2 : (buf == 1) ? zB2 : zC2;
        int idx = (r < 15) ? r : (ZH/4 - 30 + r);
        z[idx] = make_uint2(0u, 0u);
    }
    __syncthreads();

    // projection (in-place on zA): z0[p] = h[p] @ W; es/ed scores
    for (int p = t; p < LSEQ; p += GT) {
        uint2 hr[5];
        #pragma unroll
        for (int q = 0; q < 5; q++) hr[q] = zA2[(p+3)*5 + q];
        const __half* hh = reinterpret_cast<const __half*>(hr);
        float zr[CLS];
        #pragma unroll
        for (int c = 0; c < CLS; c++) zr[c] = 0.f;
        #pragma unroll
        for (int c2 = 0; c2 < CLS; c2++) {
            float hv = __half2float(hh[c2]);
            #pragma unroll
            for (int c = 0; c < CLS; c++)
                zr[c] = fmaf(hv, Wb[c2*CLS + c], zr[c]);
        }
        float es = 0.f, ed = 0.f;
        #pragma unroll
        for (int c = 0; c < CLS; c++) {
            es = fmaf(zr[c], asb[c], es);
            ed = fmaf(zr[c], adb[c], ed);
        }
        esb[p] = es; edb[p] = ed;
        #pragma unroll
        for (int q = 0; q < 5; q++) {
            __half2 lo = __floats2half2_rn(zr[q*4+0], zr[q*4+1]);
            __half2 hi = __floats2half2_rn(zr[q*4+2], zr[q*4+3]);
            uint2 u;
            u.x = *reinterpret_cast<uint32_t*>(&lo);
            u.y = *reinterpret_cast<uint32_t*>(&hi);
            zA2[(p+3)*5 + q] = u;
        }
    }
    __syncthreads();

    // banded softmax -> att planes
    for (int p = t; p < LSEQ; p += GT) {
        float ed = edb[p];
        float e[WIN], m = -1e30f;
        #pragma unroll
        for (int w = 0; w < WIN; w++) {
            int j = p - NGW + w;
            bool valid = (j >= 0) & (j < LSEQ);
            int jj = valid ? j : p;
            float ev = esb[jj] + ed;
            ev = ev > 0.f ? ev : 0.2f*ev;
            e[w] = valid ? ev : -1e30f;
            m = fmaxf(m, e[w]);
        }
        float ex[WIN], s = 0.f;
        #pragma unroll
        for (int w = 0; w < WIN; w++) {
            ex[w] = (e[w] > -1e29f) ? expf(e[w] - m) : 0.f;
            s += ex[w];
        }
        float inv = 1.f / (s + 1e-9f);
        reinterpret_cast<float4*>(att0)[p] =
            make_float4(ex[0]*inv, ex[1]*inv, ex[2]*inv, ex[3]*inv);
        reinterpret_cast<float4*>(att1)[p] =
            make_float4(ex[4]*inv, ex[5]*inv, ex[6]*inv, 0.f);
    }
    __syncthreads();

    // hops: zA -> zB -> zC -> gmem atomics; fp16 taps converted per-tap
    float* dsb = dst + (size_t)doc*LSEQ*CLS;
    #pragma unroll
    for (int hop = 0; hop < KHOPS; hop++) {
        const uint2* zin2 = (hop == 0) ? zA2 : ((hop == 1) ? zB2 : zC2);
        uint2*      zout2 = (hop == 0) ? zB2 : zC2;
        for (int j = t; j < LSEQ*CLS/4; j += GT) {
            int p = j / 5;
            int g = j - p*5;
            float4 a0 = reinterpret_cast<const float4*>(att0)[p];
            float4 a1 = reinterpret_cast<const float4*>(att1)[p];
            const uint2* zi = zin2 + p*5 + g;
            float aw[WIN] = {a0.x, a0.y, a0.z, a0.w, a1.x, a1.y, a1.z};
            float4 acc = make_float4(0.f, 0.f, 0.f, 0.f);
            #pragma unroll
            for (int w = 0; w < WIN; w++) {
                uint2 u = zi[w*5];
                float2 lo = __half22float2(*reinterpret_cast<__half2*>(&u.x));
                float2 hi = __half22float2(*reinterpret_cast<__half2*>(&u.y));
                acc.x = fmaf(aw[w], lo.x, acc.x);
                acc.y = fmaf(aw[w], lo.y, acc.y);
                acc.z = fmaf(aw[w], hi.x, acc.z);
                acc.w = fmaf(aw[w], hi.y, acc.w);
            }
            uint2 uz = zA2[(p+3)*5 + g];
            float2 zlo = __half22float2(*reinterpret_cast<__half2*>(&uz.x));
            float2 zhi = __half22float2(*reinterpret_cast<__half2*>(&uz.y));
            float4 v;
            v.x = fmaf(1.f - ALPHA, acc.x, ALPHA*zlo.x);
            v.y = fmaf(1.f - ALPHA, acc.y, ALPHA*zlo.y);
            v.z = fmaf(1.f - ALPHA, acc.z, ALPHA*zhi.x);
            v.w = fmaf(1.f - ALPHA, acc.w, ALPHA*zhi.y);
            if (hop == KHOPS-1) {
                float* o = dsb + p*CLS + g*4;
                float ex0 = (v.x > 0.f) ? v.x : expm1f(v.x);
                float ex1 = (v.y > 0.f) ? v.y : expm1f(v.y);
                float ex2 = (v.z > 0.f) ? v.z : expm1f(v.z);
                float ex3 = (v.w > 0.f) ? v.w : expm1f(v.w);
                atomicAdd(o+0, ex0 * (1.f/HEADS));
                atomicAdd(o+1, ex1 * (1.f/HEADS));
                atomicAdd(o+2, ex2 * (1.f/HEADS));
                atomicAdd(o+3, ex3 * (1.f/HEADS));
            } else {
                __half2 lo = __floats2half2_rn(v.x, v.y);
                __half2 hi = __floats2half2_rn(v.z, v.w);
                uint2 u;
                u.x = *reinterpret_cast<uint32_t*>(&lo);
                u.y = *reinterpret_cast<uint32_t*>(&hi);
                zout2[(p+3)*5 + g] = u;
            }
        }
        if (hop < KHOPS-1) __syncthreads();
    }
}

// ---------------- K4: gated readout ----------------
__global__ __launch_bounds__(256) void k_readout(
    const float* __restrict__ w_gate, const float* __restrict__ b_gate,
    float* __restrict__ out)
{
    __shared__ float wg[CLS];
    __shared__ float sred[240];
    const int t = threadIdx.x;
    if (t < CLS) wg[t] = w_gate[t];
    __syncthreads();
    const int doc = blockIdx.x;
    const float bg = b_gate[0];
    float acc = 0.f;
    if (t < 240) {
        int c = t % CLS, r = t / CLS;
        for (int p = r; p < LSEQ; p += 12) {
            const float* hr = g_h + (doc*LSEQ + p)*CLS;
            float dot = bg;
            #pragma unroll
            for (int k = 0; k < CLS; k++) dot = fmaf(hr[k], wg[k], dot);
            float gate = 1.f / (1.f + expf(-dot));
            acc = fmaf(gate, hr[c], acc);
        }
        sred[t] = acc;
    }
    __syncthreads();
    if (t < CLS) {
        float s = 0.f;
        #pragma unroll
        for (int r = 0; r < 12; r++) s += sred[r*CLS + t];
        out[doc*CLS + t] = s;
    }
}

// ---------------- launch ----------------
extern "C" void kernel_launch(void* const* d_in, const int* in_sizes, int n_in,
                              void* d_out, int out_size)
{
    const int*   node_ids = (const int*)  d_in[0];
    const float* emb    = (const float*) d_in[4];
    const float* W1     = (const float*) d_in[5];
    const float* b1     = (const float*) d_in[6];
    const float* W2     = (const float*) d_in[7];
    const float* b2     = (const float*) d_in[8];
    const float* gat_W  = (const float*) d_in[9];
    const float* a_src  = (const float*) d_in[10];
    const float* a_dst  = (const float*) d_in[11];
    const float* w_gate = (const float*) d_in[12];
    const float* b_gate = (const float*) d_in[13];
    float* out = (float*)d_out;

    cudaFuncSetAttribute(k_gemm1tc,
        cudaFuncAttributeMaxDynamicSharedMemorySize, GEMM_SMEM);
    cudaFuncSetAttribute(k_gat,
        cudaFuncAttributeMaxDynamicSharedMemorySize, GAT_SMEM);

    k_prepw<<<DIM, 256>>>(W1);                                           // 768
    k_gemm1tc<<<NNODES/TM, 256, GEMM_SMEM>>>(node_ids, emb, b1, W2, b2); // 280
    for (int l = 0; l < LAYERS; l++) {
        if (l > 0) k_zero<<<NNODES*CLS/1024, 256>>>(0);                  // zero g_h
        k_gat<<<B_DOCS*HEADS, GT, GAT_SMEM>>>(gat_W, a_src, a_dst, l);   // 1024
    }
    k_readout<<<B_DOCS, 256>>>(w_gate, b_gate, out);
}

// round 16
// speedup vs baseline: 1.2263x; 1.0361x over previous
#include <cuda_runtime.h>
#include <cuda_fp16.h>
#include <math.h>
#include <stdint.h>

// ---------------- problem constants ----------------
#define VOCAB   50000
#define B_DOCS  128
#define LSEQ    350
#define NGW     3
#define DIM     768
#define HID     256
#define CLS     20
#define HEADS   8
#define LAYERS  2
#define KHOPS   3
#define ALPHA   0.15f
#define NNODES  (B_DOCS*LSEQ)      // 44800
#define WIN     7

// ---------------- scratch ----------------
__device__ float g_h [NNODES*CLS];                 // node features (ping)
__device__ float g_hB[NNODES*CLS];                 // node features (pong)
__device__ __align__(1024) __half g_Wt[HID*DIM];   // W1^T fp16, pre-swizzled 16KB tiles

// ---------------- helpers ----------------
__device__ __forceinline__ uint32_t smem_u32(const void* p) {
    uint32_t a;
    asm("{ .reg .u64 t; cvta.to.shared.u64 t, %1; cvt.u32.u64 %0, t; }"
        : "=r"(a) : "l"(p));
    return a;
}
#define SWZ64(o) ((o) ^ (((o) >> 3) & 0x30))

__device__ __forceinline__ void ldsm4(uint32_t* r, uint32_t addr) {
    asm volatile("ldmatrix.sync.aligned.m8n8.x4.shared.b16 {%0,%1,%2,%3}, [%4];"
        : "=r"(r[0]), "=r"(r[1]), "=r"(r[2]), "=r"(r[3]) : "r"(addr));
}
__device__ __forceinline__ void mma16816(float* c, const uint32_t* a, const uint32_t* b) {
    asm volatile("mma.sync.aligned.m16n8k16.row.col.f32.f16.f16.f32 "
        "{%0,%1,%2,%3}, {%4,%5,%6,%7}, {%8,%9}, {%0,%1,%2,%3};"
        : "+f"(c[0]), "+f"(c[1]), "+f"(c[2]), "+f"(c[3])
        : "r"(a[0]), "r"(a[1]), "r"(a[2]), "r"(a[3]), "r"(b[0]), "r"(b[1]));
}
__device__ __forceinline__ void cpasync16(uint32_t dst, const void* src) {
    size_t gs = __cvta_generic_to_global(src);
    asm volatile("cp.async.cg.shared.global [%0], [%1], 16;"
                 :: "r"(dst), "l"(gs) : "memory");
}
#define CP_COMMIT() asm volatile("cp.async.commit_group;" ::: "memory")
#define CP_WAIT0()  asm volatile("cp.async.wait_group 0;" ::: "memory")
#define CP_WAIT1()  asm volatile("cp.async.wait_group 1;" ::: "memory")
#define CP_WAIT2()  asm volatile("cp.async.wait_group 2;" ::: "memory")
__device__ __forceinline__ void bulk_g2s(uint32_t dst, const void* src,
                                         uint32_t bytes, uint32_t mbar) {
    size_t gs = __cvta_generic_to_global(src);
    asm volatile(
        "cp.async.bulk.shared::cluster.global.mbarrier::complete_tx::bytes "
        "[%0], [%1], %2, [%3];"
        :: "r"(dst), "l"(gs), "r"(bytes), "r"(mbar) : "memory");
}
#define MBAR_INIT(a,c) asm volatile("mbarrier.init.shared.b64 [%0], %1;" \
    :: "r"(a), "r"(c) : "memory")
#define MBAR_EXPECT(a,tx) asm volatile( \
    "mbarrier.arrive.expect_tx.shared.b64 _, [%0], %1;" \
    :: "r"(a), "r"(tx) : "memory")
#define MBAR_WAIT(addr, par) do { \
    asm volatile("{\n\t.reg .pred P1;\n\tWAIT_%=:\n\t" \
        "mbarrier.try_wait.parity.acquire.cta.shared::cta.b64 P1, [%0], %1;\n\t" \
        "@P1 bra.uni DONE_%=;\n\tbra.uni WAIT_%=;\n\tDONE_%=:\n\t}" \
        :: "r"(addr), "r"(par) : "memory"); } while (0)
#define FENCE_ASYNC() asm volatile("fence.proxy.async.shared::cta;" ::: "memory")

// ---------------- K0: W1 -> fp16 transposed, pre-swizzled SW64 16KB tiles
__global__ __launch_bounds__(256) void k_prepw(const float* __restrict__ W1)
{
    const int k = blockIdx.x;          // 0..767
    const int n = threadIdx.x;         // 0..255
    float v = W1[k*HID + n];
    int ch = k >> 5, kk = k & 31;
    uint32_t byte = SWZ64((uint32_t)(n*64 + kk*2));
    g_Wt[(((uint32_t)ch*16384) + byte) >> 1] = __float2half_rn(v);
}

// ---------------- K1: gather + GEMM1(fp16 mma) + GEMM2 fused (R14) -------
#define TM       160
#define KB       32
#define NCH      (DIM/KB)        // 24
#define OFF_ROWS 0
#define OFF_B1   768
#define OFF_B2   1792
#define OFF_MBAR 1920            // 3 x 8B mbarriers
#define OFF_AS   2048            // A fp16:   3 x 10240 -> 32768
#define OFF_AR   32768           // A raw:    3 x 20480 -> 94208
#define OFF_BB   94208           // B fp16:   3 x 16384 -> 143360
#define XS_STRIDE 259
#define OFF_XS   2048
#define OFF_W2S  167808
#define OFF_HRED 188288
#define GEMM_SMEM 213888

__device__ __forceinline__ uint32_t a_addr64(uint32_t base, int row0, int kb, int lane) {
    int q = lane >> 3, lr = lane & 7;
    int row = row0 + ((q & 1) << 3) + lr;
    int k   = kb + ((q >> 1) << 3);
    return base + SWZ64((uint32_t)(row*64 + k*2));
}
__device__ __forceinline__ uint32_t b_addr64(uint32_t base, int n0, int kb, int lane) {
    int q = lane >> 3, lr = lane & 7;
    int n = n0 + ((q >> 1) << 3) + lr;
    int k = kb + ((q & 1) << 3);
    return base + SWZ64((uint32_t)(n*64 + k*2));
}

__device__ __forceinline__ void issue_A(
    uint32_t sb, const float* __restrict__ emb, const int* rows_s, int ch, int t)
{
    const uint32_t adst = sb + OFF_AR + (uint32_t)(ch % 3)*20480;
    const int k0 = ch * KB;
    #pragma unroll
    for (int i = 0; i < 5; i++) {
        int idx = t + i*256;               // 1280 = 160m x 8c
        int m = idx >> 3, c = idx & 7;
        cpasync16(adst + (uint32_t)(m*128 + c*16),
                  emb + (size_t)rows_s[m]*DIM + k0 + c*4);
    }
}

__device__ __forceinline__ void convert_chunk(char* smc, int slot, int t)
{
    const char* raw = smc + OFF_AR + slot*20480;
    char* dH = smc + OFF_AS + slot*10240;
    #pragma unroll
    for (int i = 0; i < 5; i++) {
        int idx = t + i*256;
        int m = idx >> 3, g = idx & 7;
        float4 v = *reinterpret_cast<const float4*>(raw + m*128 + g*16);
        __half2 h0 = __float22half2_rn(make_float2(v.x, v.y));
        __half2 h1 = __float22half2_rn(make_float2(v.z, v.w));
        uint2 hv;
        hv.x = *reinterpret_cast<uint32_t*>(&h0);
        hv.y = *reinterpret_cast<uint32_t*>(&h1);
        *reinterpret_cast<uint2*>(dH + SWZ64((uint32_t)(m*64 + g*8))) = hv;
    }
}

__global__ __launch_bounds__(256, 1) void k_gemm1tc(
    const int* __restrict__ node_ids, const float* __restrict__ emb,
    const float* __restrict__ b1, const float* __restrict__ W2,
    const float* __restrict__ b2)
{
    extern __shared__ char smc[];
    const uint32_t sb = smem_u32(smc);
    const int t = threadIdx.x, lane = t & 31, wid = t >> 5;
    const int wm = wid >> 2, wn = wid & 3;       // 2 x 4 warps
    const int m0 = blockIdx.x * TM;
    int*   rows_s = (int*)(smc + OFF_ROWS);
    float* b1s    = (float*)(smc + OFF_B1);
    float* b2s    = (float*)(smc + OFF_B2);

    if (t < TM) rows_s[t] = node_ids[m0 + t];
    b1s[t] = b1[t];
    if (t < CLS) b2s[t] = b2[t];

    {
        float4* zb = reinterpret_cast<float4*>(g_hB + (size_t)m0*CLS);
        #pragma unroll
        for (int i = t; i < TM*CLS/4; i += 256)
            zb[i] = make_float4(0.f, 0.f, 0.f, 0.f);
    }
    if (t == 0) {
        MBAR_INIT(sb + OFF_MBAR,      1);
        MBAR_INIT(sb + OFF_MBAR + 8,  1);
        MBAR_INIT(sb + OFF_MBAR + 16, 1);
    }
    __syncthreads();
    FENCE_ASYNC();
    if (t == 0) {
        MBAR_EXPECT(sb + OFF_MBAR,      16384);
        MBAR_EXPECT(sb + OFF_MBAR + 8,  16384);
        MBAR_EXPECT(sb + OFF_MBAR + 16, 16384);
    }
    __syncthreads();

    issue_A(sb, emb, rows_s, 0, t); CP_COMMIT();
    issue_A(sb, emb, rows_s, 1, t); CP_COMMIT();
    issue_A(sb, emb, rows_s, 2, t); CP_COMMIT();
    if (t == 0) {
        bulk_g2s(sb + OFF_BB,         g_Wt,         16384, sb + OFF_MBAR);
        bulk_g2s(sb + OFF_BB + 16384, g_Wt + 8192,  16384, sb + OFF_MBAR + 8);
        bulk_g2s(sb + OFF_BB + 32768, g_Wt + 16384, 16384, sb + OFF_MBAR + 16);
    }
    CP_WAIT2();
    convert_chunk(smc, 0, t);
    __syncthreads();

    float acc[5][8][4];
    #pragma unroll
    for (int mt = 0; mt < 5; mt++)
        #pragma unroll
        for (int nt = 0; nt < 8; nt++)
            #pragma unroll
            for (int q = 0; q < 4; q++) acc[mt][nt][q] = 0.f;

    for (int ch = 0; ch < NCH; ch++) {
        const int slot = ch % 3;
        if (ch + 1 < NCH) {
            if (ch + 2 < NCH) CP_WAIT1(); else CP_WAIT0();
            convert_chunk(smc, (ch + 1) % 3, t);
        }
        MBAR_WAIT(sb + OFF_MBAR + slot*8, (uint32_t)((ch / 3) & 1));
        const uint32_t aH = sb + OFF_AS + slot*10240;
        const uint32_t bH = sb + OFF_BB + slot*16384;
        #pragma unroll
        for (int ks = 0; ks < 2; ks++) {
            const int kb = ks*16;
            uint32_t af[5][4], bf[8][2];
            #pragma unroll
            for (int mt = 0; mt < 5; mt++)
                ldsm4(af[mt], a_addr64(aH, wm*80 + mt*16, kb, lane));
            #pragma unroll
            for (int p = 0; p < 4; p++) {
                uint32_t r[4];
                ldsm4(r, b_addr64(bH, wn*64 + p*16, kb, lane));
                bf[p*2][0]=r[0]; bf[p*2][1]=r[1];
                bf[p*2+1][0]=r[2]; bf[p*2+1][1]=r[3];
            }
            #pragma unroll
            for (int mt = 0; mt < 5; mt++)
                #pragma unroll
                for (int nt = 0; nt < 8; nt++)
                    mma16816(acc[mt][nt], af[mt], bf[nt]);
        }
        __syncthreads();
        if (ch + 3 < NCH) {
            issue_A(sb, emb, rows_s, ch + 3, t);
            CP_COMMIT();
            if (t == 0) {
                MBAR_EXPECT(sb + OFF_MBAR + slot*8, 16384);
                bulk_g2s(sb + OFF_BB + slot*16384, g_Wt + (ch + 3)*8192,
                         16384, sb + OFF_MBAR + slot*8);
            }
        }
    }
    __syncthreads();

    float* XS = (float*)(smc + OFF_XS);
    {
        const int lr4 = lane >> 2, lc2 = (lane & 3)*2;
        #pragma unroll
        for (int mt = 0; mt < 5; mt++) {
            #pragma unroll
            for (int nt = 0; nt < 8; nt++) {
                int r0 = wm*80 + mt*16 + lr4;
                int c0 = wn*64 + nt*8 + lc2;
                float ba = b1s[c0], bb = b1s[c0+1];
                XS[r0*XS_STRIDE + c0]       = fmaxf(acc[mt][nt][0] + ba, 0.f);
                XS[r0*XS_STRIDE + c0 + 1]   = fmaxf(acc[mt][nt][1] + bb, 0.f);
                XS[(r0+8)*XS_STRIDE + c0]   = fmaxf(acc[mt][nt][2] + ba, 0.f);
                XS[(r0+8)*XS_STRIDE + c0+1] = fmaxf(acc[mt][nt][3] + bb, 0.f);
            }
        }
    }
    float* W2S  = (float*)(smc + OFF_W2S);
    float* HRED = (float*)(smc + OFF_HRED);
    for (int i = t; i < HID*CLS; i += 256) W2S[i] = W2[i];
    __syncthreads();

    for (int p = t; p < 2*TM; p += 256) {
        int half = p / TM, row = p - half*TM;
        float hacc[CLS];
        #pragma unroll
        for (int c = 0; c < CLS; c++) hacc[c] = 0.f;
        const float* xr = XS + row*XS_STRIDE + half*128;
        #pragma unroll 4
        for (int n = 0; n < 128; n++) {
            float xv = xr[n];
            const float4* w4 = reinterpret_cast<const float4*>(
                W2S + (half*128 + n)*CLS);
            #pragma unroll
            for (int q = 0; q < 5; q++) {
                float4 w = w4[q];
                hacc[q*4+0] = fmaf(xv, w.x, hacc[q*4+0]);
                hacc[q*4+1] = fmaf(xv, w.y, hacc[q*4+1]);
                hacc[q*4+2] = fmaf(xv, w.z, hacc[q*4+2]);
                hacc[q*4+3] = fmaf(xv, w.w, hacc[q*4+3]);
            }
        }
        #pragma unroll
        for (int c = 0; c < CLS; c++) HRED[p*CLS + c] = hacc[c];
    }
    __syncthreads();
    if (t < TM) {
        #pragma unroll
        for (int c = 0; c < CLS; c++)
            g_h[(m0 + t)*CLS + c] =
                HRED[t*CLS + c] + HRED[(TM + t)*CLS + c] + b2s[c];
    }
}

// ---------------- K2: zero a feature buffer ----------------
__global__ __launch_bounds__(256) void k_zero(int which)
{
    float* p = which ? g_hB : g_h;
    int i = blockIdx.x*256 + threadIdx.x;
    reinterpret_cast<float4*>(p)[i] = make_float4(0.f, 0.f, 0.f, 0.f);
}

// ---------------- K3: fused GAT layer, fp16 z + half2 stencil math -------
#define GT 512
#define ZROWS 356
#define ZH    (ZROWS*CLS)          // 7120 halves per buffer
#define GAT_SMEM 53248
__global__ __launch_bounds__(GT, 3) void k_gat(
    const float* __restrict__ gat_W, const float* __restrict__ a_src,
    const float* __restrict__ a_dst, int layer)
{
    extern __shared__ char gsm[];
    __half* zA = (__half*)gsm;           // h, then z0 (persists)
    __half* zB = zA + ZH;
    __half* zC = zB + ZH;
    uint2* a0h  = (uint2*)(gsm + 42720); // att halves w0..w3, 350 x 8B
    uint2* a1h  = a0h + 350;             // att halves w4..w6,0
    float* esb  = (float*)(a1h + 350);   // 352
    float* edb  = esb + 352;             // 352
    float* Wb   = edb + 352;             // 400
    float* asb  = Wb + 400;              // 20
    float* adb  = asb + 20;              // 20
    const int t = threadIdx.x;
    const int hd = blockIdx.x & 7, doc = blockIdx.x >> 3;
    const float* src = (layer == 0) ? g_h : g_hB;
    float*       dst = (layer == 0) ? g_hB : g_h;

    uint2* zA2 = reinterpret_cast<uint2*>(zA);
    uint2* zB2 = reinterpret_cast<uint2*>(zB);
    uint2* zC2 = reinterpret_cast<uint2*>(zC);

    // load h -> fp16 into zA rows 3..352
    const float4* hg = reinterpret_cast<const float4*>(src + (size_t)doc*LSEQ*CLS);
    for (int i = t; i < LSEQ*CLS/4; i += GT) {
        float4 v = hg[i];
        __half2 lo = __floats2half2_rn(v.x, v.y);
        __half2 hi = __floats2half2_rn(v.z, v.w);
        uint2 u;
        u.x = *reinterpret_cast<uint32_t*>(&lo);
        u.y = *reinterpret_cast<uint32_t*>(&hi);
        zA2[i + 15] = u;
    }
    const float* Wg = gat_W + ((size_t)layer*HEADS + hd)*CLS*CLS;
    for (int i = t; i < CLS*CLS; i += GT) Wb[i] = Wg[i];
    if (t >= GT-32 && t < GT-32+CLS) {
        int c = t - (GT-32);
        asb[c] = a_src[(layer*HEADS + hd)*CLS + c];
        adb[c] = a_dst[(layer*HEADS + hd)*CLS + c];
    }
    // zero halos
    if (t >= GT-128 && t < GT-128+90) {
        int r0 = t - (GT-128);
        int buf = r0 / 30, r = r0 % 30;
        uint2* z = (buf == 0) ? zA2 : (buf == 1) ? zB2 : zC2;
        int idx = (r < 15) ? r : (ZH/4 - 30 + r);
        z[idx] = make_uint2(0u, 0u);
    }
    __syncthreads();

    // projection (in-place on zA): z0[p] = h[p] @ W; es/ed scores
    for (int p = t; p < LSEQ; p += GT) {
        uint2 hr[5];
        #pragma unroll
        for (int q = 0; q < 5; q++) hr[q] = zA2[(p+3)*5 + q];
        const __half* hh = reinterpret_cast<const __half*>(hr);
        float zr[CLS];
        #pragma unroll
        for (int c = 0; c < CLS; c++) zr[c] = 0.f;
        #pragma unroll
        for (int c2 = 0; c2 < CLS; c2++) {
            float hv = __half2float(hh[c2]);
            #pragma unroll
            for (int c = 0; c < CLS; c++)
                zr[c] = fmaf(hv, Wb[c2*CLS + c], zr[c]);
        }
        float es = 0.f, ed = 0.f;
        #pragma unroll
        for (int c = 0; c < CLS; c++) {
            es = fmaf(zr[c], asb[c], es);
            ed = fmaf(zr[c], adb[c], ed);
        }
        esb[p] = es; edb[p] = ed;
        #pragma unroll
        for (int q = 0; q < 5; q++) {
            __half2 lo = __floats2half2_rn(zr[q*4+0], zr[q*4+1]);
            __half2 hi = __floats2half2_rn(zr[q*4+2], zr[q*4+3]);
            uint2 u;
            u.x = *reinterpret_cast<uint32_t*>(&lo);
            u.y = *reinterpret_cast<uint32_t*>(&hi);
            zA2[(p+3)*5 + q] = u;
        }
    }
    __syncthreads();

    // banded softmax -> att half2 planes
    for (int p = t; p < LSEQ; p += GT) {
        float ed = edb[p];
        float e[WIN], m = -1e30f;
        #pragma unroll
        for (int w = 0; w < WIN; w++) {
            int j = p - NGW + w;
            bool valid = (j >= 0) & (j < LSEQ);
            int jj = valid ? j : p;
            float ev = esb[jj] + ed;
            ev = ev > 0.f ? ev : 0.2f*ev;
            e[w] = valid ? ev : -1e30f;
            m = fmaxf(m, e[w]);
        }
        float ex[WIN], s = 0.f;
        #pragma unroll
        for (int w = 0; w < WIN; w++) {
            ex[w] = (e[w] > -1e29f) ? expf(e[w] - m) : 0.f;
            s += ex[w];
        }
        float inv = 1.f / (s + 1e-9f);
        __half2 w01 = __floats2half2_rn(ex[0]*inv, ex[1]*inv);
        __half2 w23 = __floats2half2_rn(ex[2]*inv, ex[3]*inv);
        __half2 w45 = __floats2half2_rn(ex[4]*inv, ex[5]*inv);
        __half2 w6x = __floats2half2_rn(ex[6]*inv, 0.f);
        uint2 u0, u1;
        u0.x = *reinterpret_cast<uint32_t*>(&w01);
        u0.y = *reinterpret_cast<uint32_t*>(&w23);
        u1.x = *reinterpret_cast<uint32_t*>(&w45);
        u1.y = *reinterpret_cast<uint32_t*>(&w6x);
        a0h[p] = u0;
        a1h[p] = u1;
    }
    __syncthreads();

    // hops: half2 stencil FMAs; fp32 blend + ELU
    float* dsb = dst + (size_t)doc*LSEQ*CLS;
    #pragma unroll
    for (int hop = 0; hop < KHOPS; hop++) {
        const uint2* zin2 = (hop == 0) ? zA2 : ((hop == 1) ? zB2 : zC2);
        uint2*      zout2 = (hop == 0) ? zB2 : zC2;
        for (int j = t; j < LSEQ*CLS/4; j += GT) {
            int p = j / 5;
            int g = j - p*5;
            uint2 ua = a0h[p], ub = a1h[p];
            __half2 a01 = *reinterpret_cast<__half2*>(&ua.x);
            __half2 a23 = *reinterpret_cast<__half2*>(&ua.y);
            __half2 a45 = *reinterpret_cast<__half2*>(&ub.x);
            __half2 a6x = *reinterpret_cast<__half2*>(&ub.y);
            __half2 b0 = __low2half2(a01), b1 = __high2half2(a01);
            __half2 b2 = __low2half2(a23), b3 = __high2half2(a23);
            __half2 b4 = __low2half2(a45), b5 = __high2half2(a45);
            __half2 b6 = __low2half2(a6x);
            const uint2* zi = zin2 + p*5 + g;
            uint2 t0 = zi[0],  t1 = zi[5],  t2 = zi[10], t3 = zi[15];
            uint2 t4 = zi[20], t5 = zi[25], t6 = zi[30];
            #define H2(u) (*reinterpret_cast<__half2*>(&(u)))
            __half2 accL = __hmul2(b0, H2(t0.x));
            __half2 accH = __hmul2(b0, H2(t0.y));
            accL = __hfma2(b1, H2(t1.x), accL); accH = __hfma2(b1, H2(t1.y), accH);
            accL = __hfma2(b2, H2(t2.x), accL); accH = __hfma2(b2, H2(t2.y), accH);
            accL = __hfma2(b3, H2(t3.x), accL); accH = __hfma2(b3, H2(t3.y), accH);
            accL = __hfma2(b4, H2(t4.x), accL); accH = __hfma2(b4, H2(t4.y), accH);
            accL = __hfma2(b5, H2(t5.x), accL); accH = __hfma2(b5, H2(t5.y), accH);
            accL = __hfma2(b6, H2(t6.x), accL); accH = __hfma2(b6, H2(t6.y), accH);
            #undef H2
            float2 aL = __half22float2(accL);
            float2 aH = __half22float2(accH);
            uint2 uz = zA2[(p+3)*5 + g];
            float2 zlo = __half22float2(*reinterpret_cast<__half2*>(&uz.x));
            float2 zhi = __half22float2(*reinterpret_cast<__half2*>(&uz.y));
            float4 v;
            v.x = fmaf(1.f - ALPHA, aL.x, ALPHA*zlo.x);
            v.y = fmaf(1.f - ALPHA, aL.y, ALPHA*zlo.y);
            v.z = fmaf(1.f - ALPHA, aH.x, ALPHA*zhi.x);
            v.w = fmaf(1.f - ALPHA, aH.y, ALPHA*zhi.y);
            if (hop == KHOPS-1) {
                float* o = dsb + p*CLS + g*4;
                float ex0 = (v.x > 0.f) ? v.x : expm1f(v.x);
                float ex1 = (v.y > 0.f) ? v.y : expm1f(v.y);
                float ex2 = (v.z > 0.f) ? v.z : expm1f(v.z);
                float ex3 = (v.w > 0.f) ? v.w : expm1f(v.w);
                atomicAdd(o+0, ex0 * (1.f/HEADS));
                atomicAdd(o+1, ex1 * (1.f/HEADS));
                atomicAdd(o+2, ex2 * (1.f/HEADS));
                atomicAdd(o+3, ex3 * (1.f/HEADS));
            } else {
                __half2 lo = __floats2half2_rn(v.x, v.y);
                __half2 hi = __floats2half2_rn(v.z, v.w);
                uint2 u;
                u.x = *reinterpret_cast<uint32_t*>(&lo);
                u.y = *reinterpret_cast<uint32_t*>(&hi);
                zout2[(p+3)*5 + g] = u;
            }
        }
        if (hop < KHOPS-1) __syncthreads();
    }
}

// ---------------- K4: gated readout ----------------
__global__ __launch_bounds__(256) void k_readout(
    const float* __restrict__ w_gate, const float* __restrict__ b_gate,
    float* __restrict__ out)
{
    __shared__ float wg[CLS];
    __shared__ float sred[240];
    const int t = threadIdx.x;
    if (t < CLS) wg[t] = w_gate[t];
    __syncthreads();
    const int doc = blockIdx.x;
    const float bg = b_gate[0];
    float acc = 0.f;
    if (t < 240) {
        int c = t % CLS, r = t / CLS;
        for (int p = r; p < LSEQ; p += 12) {
            const float* hr = g_h + (doc*LSEQ + p)*CLS;
            float dot = bg;
            #pragma unroll
            for (int k = 0; k < CLS; k++) dot = fmaf(hr[k], wg[k], dot);
            float gate = 1.f / (1.f + expf(-dot));
            acc = fmaf(gate, hr[c], acc);
        }
        sred[t] = acc;
    }
    __syncthreads();
    if (t < CLS) {
        float s = 0.f;
        #pragma unroll
        for (int r = 0; r < 12; r++) s += sred[r*CLS + t];
        out[doc*CLS + t] = s;
    }
}

// ---------------- launch ----------------
extern "C" void kernel_launch(void* const* d_in, const int* in_sizes, int n_in,
                              void* d_out, int out_size)
{
    const int*   node_ids = (const int*)  d_in[0];
    const float* emb    = (const float*) d_in[4];
    const float* W1     = (const float*) d_in[5];
    const float* b1     = (const float*) d_in[6];
    const float* W2     = (const float*) d_in[7];
    const float* b2     = (const float*) d_in[8];
    const float* gat_W  = (const float*) d_in[9];
    const float* a_src  = (const float*) d_in[10];
    const float* a_dst  = (const float*) d_in[11];
    const float* w_gate = (const float*) d_in[12];
    const float* b_gate = (const float*) d_in[13];
    float* out = (float*)d_out;

    cudaFuncSetAttribute(k_gemm1tc,
        cudaFuncAttributeMaxDynamicSharedMemorySize, GEMM_SMEM);
    cudaFuncSetAttribute(k_gat,
        cudaFuncAttributeMaxDynamicSharedMemorySize, GAT_SMEM);

    k_prepw<<<DIM, 256>>>(W1);                                           // 768
    k_gemm1tc<<<NNODES/TM, 256, GEMM_SMEM>>>(node_ids, emb, b1, W2, b2); // 280
    for (int l = 0; l < LAYERS; l++) {
        if (l > 0) k_zero<<<NNODES*CLS/1024, 256>>>(0);                  // zero g_h
        k_gat<<<B_DOCS*HEADS, GT, GAT_SMEM>>>(gat_W, a_src, a_dst, l);   // 1024
    }
    k_readout<<<B_DOCS, 256>>>(w_gate, b_gate, out);
}

// round 17
// speedup vs baseline: 1.2392x; 1.0105x over previous
#include <cuda_runtime.h>
#include <cuda_fp16.h>
#include <math.h>
#include <stdint.h>

// ---------------- problem constants ----------------
#define VOCAB   50000
#define B_DOCS  128
#define LSEQ    350
#define NGW     3
#define DIM     768
#define HID     256
#define CLS     20
#define HEADS   8
#define LAYERS  2
#define KHOPS   3
#define ALPHA   0.15f
#define NNODES  (B_DOCS*LSEQ)      // 44800
#define WIN     7

// ---------------- scratch ----------------
__device__ float g_h [NNODES*CLS];                 // node features (ping)
__device__ float g_hB[NNODES*CLS];                 // node features (pong)
__device__ __align__(1024) __half g_Wt[HID*DIM];   // W1^T fp16, pre-swizzled 16KB tiles

// ---------------- helpers ----------------
__device__ __forceinline__ uint32_t smem_u32(const void* p) {
    uint32_t a;
    asm("{ .reg .u64 t; cvta.to.shared.u64 t, %1; cvt.u32.u64 %0, t; }"
        : "=r"(a) : "l"(p));
    return a;
}
#define SWZ64(o) ((o) ^ (((o) >> 3) & 0x30))

__device__ __forceinline__ void ldsm4(uint32_t* r, uint32_t addr) {
    asm volatile("ldmatrix.sync.aligned.m8n8.x4.shared.b16 {%0,%1,%2,%3}, [%4];"
        : "=r"(r[0]), "=r"(r[1]), "=r"(r[2]), "=r"(r[3]) : "r"(addr));
}
__device__ __forceinline__ void mma16816(float* c, const uint32_t* a, const uint32_t* b) {
    asm volatile("mma.sync.aligned.m16n8k16.row.col.f32.f16.f16.f32 "
        "{%0,%1,%2,%3}, {%4,%5,%6,%7}, {%8,%9}, {%0,%1,%2,%3};"
        : "+f"(c[0]), "+f"(c[1]), "+f"(c[2]), "+f"(c[3])
        : "r"(a[0]), "r"(a[1]), "r"(a[2]), "r"(a[3]), "r"(b[0]), "r"(b[1]));
}
__device__ __forceinline__ void cpasync16(uint32_t dst, const void* src) {
    size_t gs = __cvta_generic_to_global(src);
    asm volatile("cp.async.cg.shared.global [%0], [%1], 16;"
                 :: "r"(dst), "l"(gs) : "memory");
}
#define CP_COMMIT() asm volatile("cp.async.commit_group;" ::: "memory")
#define CP_WAIT0()  asm volatile("cp.async.wait_group 0;" ::: "memory")
#define CP_WAIT1()  asm volatile("cp.async.wait_group 1;" ::: "memory")
#define CP_WAIT2()  asm volatile("cp.async.wait_group 2;" ::: "memory")
__device__ __forceinline__ void bulk_g2s(uint32_t dst, const void* src,
                                         uint32_t bytes, uint32_t mbar) {
    size_t gs = __cvta_generic_to_global(src);
    asm volatile(
        "cp.async.bulk.shared::cluster.global.mbarrier::complete_tx::bytes "
        "[%0], [%1], %2, [%3];"
        :: "r"(dst), "l"(gs), "r"(bytes), "r"(mbar) : "memory");
}
#define MBAR_INIT(a,c) asm volatile("mbarrier.init.shared.b64 [%0], %1;" \
    :: "r"(a), "r"(c) : "memory")
#define MBAR_EXPECT(a,tx) asm volatile( \
    "mbarrier.arrive.expect_tx.shared.b64 _, [%0], %1;" \
    :: "r"(a), "r"(tx) : "memory")
#define MBAR_WAIT(addr, par) do { \
    asm volatile("{\n\t.reg .pred P1;\n\tWAIT_%=:\n\t" \
        "mbarrier.try_wait.parity.acquire.cta.shared::cta.b64 P1, [%0], %1;\n\t" \
        "@P1 bra.uni DONE_%=;\n\tbra.uni WAIT_%=;\n\tDONE_%=:\n\t}" \
        :: "r"(addr), "r"(par) : "memory"); } while (0)
#define FENCE_ASYNC() asm volatile("fence.proxy.async.shared::cta;" ::: "memory")

// ---------------- K0: W1 -> fp16 transposed, pre-swizzled SW64 16KB tiles
__global__ __launch_bounds__(256) void k_prepw(const float* __restrict__ W1)
{
    const int k = blockIdx.x;          // 0..767
    const int n = threadIdx.x;         // 0..255
    float v = W1[k*HID + n];
    int ch = k >> 5, kk = k & 31;
    uint32_t byte = SWZ64((uint32_t)(n*64 + kk*2));
    g_Wt[(((uint32_t)ch*16384) + byte) >> 1] = __float2half_rn(v);
}

// ---------------- K1: gather + GEMM1(fp16 mma) + GEMM2 fused (R14) -------
#define TM       160
#define KB       32
#define NCH      (DIM/KB)        // 24
#define OFF_ROWS 0
#define OFF_B1   768
#define OFF_B2   1792
#define OFF_MBAR 1920            // 3 x 8B mbarriers
#define OFF_AS   2048            // A fp16:   3 x 10240 -> 32768
#define OFF_AR   32768           // A raw:    3 x 20480 -> 94208
#define OFF_BB   94208           // B fp16:   3 x 16384 -> 143360
#define XS_STRIDE 259
#define OFF_XS   2048
#define OFF_W2S  167808
#define OFF_HRED 188288
#define GEMM_SMEM 213888

__device__ __forceinline__ uint32_t a_addr64(uint32_t base, int row0, int kb, int lane) {
    int q = lane >> 3, lr = lane & 7;
    int row = row0 + ((q & 1) << 3) + lr;
    int k   = kb + ((q >> 1) << 3);
    return base + SWZ64((uint32_t)(row*64 + k*2));
}
__device__ __forceinline__ uint32_t b_addr64(uint32_t base, int n0, int kb, int lane) {
    int q = lane >> 3, lr = lane & 7;
    int n = n0 + ((q >> 1) << 3) + lr;
    int k = kb + ((q & 1) << 3);
    return base + SWZ64((uint32_t)(n*64 + k*2));
}

__device__ __forceinline__ void issue_A(
    uint32_t sb, const float* __restrict__ emb, const int* rows_s, int ch, int t)
{
    const uint32_t adst = sb + OFF_AR + (uint32_t)(ch % 3)*20480;
    const int k0 = ch * KB;
    #pragma unroll
    for (int i = 0; i < 5; i++) {
        int idx = t + i*256;               // 1280 = 160m x 8c
        int m = idx >> 3, c = idx & 7;
        cpasync16(adst + (uint32_t)(m*128 + c*16),
                  emb + (size_t)rows_s[m]*DIM + k0 + c*4);
    }
}

__device__ __forceinline__ void convert_chunk(char* smc, int slot, int t)
{
    const char* raw = smc + OFF_AR + slot*20480;
    char* dH = smc + OFF_AS + slot*10240;
    #pragma unroll
    for (int i = 0; i < 5; i++) {
        int idx = t + i*256;
        int m = idx >> 3, g = idx & 7;
        float4 v = *reinterpret_cast<const float4*>(raw + m*128 + g*16);
        __half2 h0 = __float22half2_rn(make_float2(v.x, v.y));
        __half2 h1 = __float22half2_rn(make_float2(v.z, v.w));
        uint2 hv;
        hv.x = *reinterpret_cast<uint32_t*>(&h0);
        hv.y = *reinterpret_cast<uint32_t*>(&h1);
        *reinterpret_cast<uint2*>(dH + SWZ64((uint32_t)(m*64 + g*8))) = hv;
    }
}

__global__ __launch_bounds__(256, 1) void k_gemm1tc(
    const int* __restrict__ node_ids, const float* __restrict__ emb,
    const float* __restrict__ b1, const float* __restrict__ W2,
    const float* __restrict__ b2)
{
    extern __shared__ char smc[];
    const uint32_t sb = smem_u32(smc);
    const int t = threadIdx.x, lane = t & 31, wid = t >> 5;
    const int wm = wid >> 2, wn = wid & 3;       // 2 x 4 warps
    const int m0 = blockIdx.x * TM;
    int*   rows_s = (int*)(smc + OFF_ROWS);
    float* b1s    = (float*)(smc + OFF_B1);
    float* b2s    = (float*)(smc + OFF_B2);

    if (t < TM) rows_s[t] = node_ids[m0 + t];
    b1s[t] = b1[t];
    if (t < CLS) b2s[t] = b2[t];

    {
        float4* zb = reinterpret_cast<float4*>(g_hB + (size_t)m0*CLS);
        #pragma unroll
        for (int i = t; i < TM*CLS/4; i += 256)
            zb[i] = make_float4(0.f, 0.f, 0.f, 0.f);
    }
    if (t == 0) {
        MBAR_INIT(sb + OFF_MBAR,      1);
        MBAR_INIT(sb + OFF_MBAR + 8,  1);
        MBAR_INIT(sb + OFF_MBAR + 16, 1);
    }
    __syncthreads();
    FENCE_ASYNC();
    if (t == 0) {
        MBAR_EXPECT(sb + OFF_MBAR,      16384);
        MBAR_EXPECT(sb + OFF_MBAR + 8,  16384);
        MBAR_EXPECT(sb + OFF_MBAR + 16, 16384);
    }
    __syncthreads();

    issue_A(sb, emb, rows_s, 0, t); CP_COMMIT();
    issue_A(sb, emb, rows_s, 1, t); CP_COMMIT();
    issue_A(sb, emb, rows_s, 2, t); CP_COMMIT();
    if (t == 0) {
        bulk_g2s(sb + OFF_BB,         g_Wt,         16384, sb + OFF_MBAR);
        bulk_g2s(sb + OFF_BB + 16384, g_Wt + 8192,  16384, sb + OFF_MBAR + 8);
        bulk_g2s(sb + OFF_BB + 32768, g_Wt + 16384, 16384, sb + OFF_MBAR + 16);
    }
    CP_WAIT2();
    convert_chunk(smc, 0, t);
    __syncthreads();

    float acc[5][8][4];
    #pragma unroll
    for (int mt = 0; mt < 5; mt++)
        #pragma unroll
        for (int nt = 0; nt < 8; nt++)
            #pragma unroll
            for (int q = 0; q < 4; q++) acc[mt][nt][q] = 0.f;

    for (int ch = 0; ch < NCH; ch++) {
        const int slot = ch % 3;
        if (ch + 1 < NCH) {
            if (ch + 2 < NCH) CP_WAIT1(); else CP_WAIT0();
            convert_chunk(smc, (ch + 1) % 3, t);
        }
        MBAR_WAIT(sb + OFF_MBAR + slot*8, (uint32_t)((ch / 3) & 1));
        const uint32_t aH = sb + OFF_AS + slot*10240;
        const uint32_t bH = sb + OFF_BB + slot*16384;
        #pragma unroll
        for (int ks = 0; ks < 2; ks++) {
            const int kb = ks*16;
            uint32_t af[5][4], bf[8][2];
            #pragma unroll
            for (int mt = 0; mt < 5; mt++)
                ldsm4(af[mt], a_addr64(aH, wm*80 + mt*16, kb, lane));
            #pragma unroll
            for (int p = 0; p < 4; p++) {
                uint32_t r[4];
                ldsm4(r, b_addr64(bH, wn*64 + p*16, kb, lane));
                bf[p*2][0]=r[0]; bf[p*2][1]=r[1];
                bf[p*2+1][0]=r[2]; bf[p*2+1][1]=r[3];
            }
            #pragma unroll
            for (int mt = 0; mt < 5; mt++)
                #pragma unroll
                for (int nt = 0; nt < 8; nt++)
                    mma16816(acc[mt][nt], af[mt], bf[nt]);
        }
        __syncthreads();
        if (ch + 3 < NCH) {
            issue_A(sb, emb, rows_s, ch + 3, t);
            CP_COMMIT();
            if (t == 0) {
                MBAR_EXPECT(sb + OFF_MBAR + slot*8, 16384);
                bulk_g2s(sb + OFF_BB + slot*16384, g_Wt + (ch + 3)*8192,
                         16384, sb + OFF_MBAR + slot*8);
            }
        }
    }
    __syncthreads();

    float* XS = (float*)(smc + OFF_XS);
    {
        const int lr4 = lane >> 2, lc2 = (lane & 3)*2;
        #pragma unroll
        for (int mt = 0; mt < 5; mt++) {
            #pragma unroll
            for (int nt = 0; nt < 8; nt++) {
                int r0 = wm*80 + mt*16 + lr4;
                int c0 = wn*64 + nt*8 + lc2;
                float ba = b1s[c0], bb = b1s[c0+1];
                XS[r0*XS_STRIDE + c0]       = fmaxf(acc[mt][nt][0] + ba, 0.f);
                XS[r0*XS_STRIDE + c0 + 1]   = fmaxf(acc[mt][nt][1] + bb, 0.f);
                XS[(r0+8)*XS_STRIDE + c0]   = fmaxf(acc[mt][nt][2] + ba, 0.f);
                XS[(r0+8)*XS_STRIDE + c0+1] = fmaxf(acc[mt][nt][3] + bb, 0.f);
            }
        }
    }
    float* W2S  = (float*)(smc + OFF_W2S);
    float* HRED = (float*)(smc + OFF_HRED);
    for (int i = t; i < HID*CLS; i += 256) W2S[i] = W2[i];
    __syncthreads();

    for (int p = t; p < 2*TM; p += 256) {
        int half = p / TM, row = p - half*TM;
        float hacc[CLS];
        #pragma unroll
        for (int c = 0; c < CLS; c++) hacc[c] = 0.f;
        const float* xr = XS + row*XS_STRIDE + half*128;
        #pragma unroll 4
        for (int n = 0; n < 128; n++) {
            float xv = xr[n];
            const float4* w4 = reinterpret_cast<const float4*>(
                W2S + (half*128 + n)*CLS);
            #pragma unroll
            for (int q = 0; q < 5; q++) {
                float4 w = w4[q];
                hacc[q*4+0] = fmaf(xv, w.x, hacc[q*4+0]);
                hacc[q*4+1] = fmaf(xv, w.y, hacc[q*4+1]);
                hacc[q*4+2] = fmaf(xv, w.z, hacc[q*4+2]);
                hacc[q*4+3] = fmaf(xv, w.w, hacc[q*4+3]);
            }
        }
        #pragma unroll
        for (int c = 0; c < CLS; c++) HRED[p*CLS + c] = hacc[c];
    }
    __syncthreads();
    if (t < TM) {
        #pragma unroll
        for (int c = 0; c < CLS; c++)
            g_h[(m0 + t)*CLS + c] =
                HRED[t*CLS + c] + HRED[(TM + t)*CLS + c] + b2s[c];
    }
}

// ---------------- K2: zero a feature buffer ----------------
__global__ __launch_bounds__(256) void k_zero(int which)
{
    float* p = which ? g_hB : g_h;
    int i = blockIdx.x*256 + threadIdx.x;
    reinterpret_cast<float4*>(p)[i] = make_float4(0.f, 0.f, 0.f, 0.f);
}

// ---------------- K3: fused GAT layer, fp16 z + half2 math, 4 CTA/SM -----
#define GT 512
#define ZROWS 356
#define ZH    (ZROWS*CLS)          // 7120 halves per buffer
#define GAT_SMEM 53248
__global__ __launch_bounds__(GT, 4) void k_gat(
    const float* __restrict__ gat_W, const float* __restrict__ a_src,
    const float* __restrict__ a_dst, int layer)
{
    extern __shared__ char gsm[];
    __half* zA = (__half*)gsm;           // h, then z0 (persists)
    __half* zB = zA + ZH;
    __half* zC = zB + ZH;
    uint2* a0h  = (uint2*)(gsm + 42720); // att halves w0..w3, 350 x 8B
    uint2* a1h  = a0h + 350;             // att halves w4..w6,0
    float* esb  = (float*)(a1h + 350);   // 352
    float* edb  = esb + 352;             // 352
    float* Wb   = edb + 352;             // 400
    float* asb  = Wb + 400;              // 20
    float* adb  = asb + 20;              // 20
    const int t = threadIdx.x;
    const int hd = blockIdx.x & 7, doc = blockIdx.x >> 3;
    const float* src = (layer == 0) ? g_h : g_hB;
    float*       dst = (layer == 0) ? g_hB : g_h;

    uint2* zA2 = reinterpret_cast<uint2*>(zA);
    uint2* zB2 = reinterpret_cast<uint2*>(zB);
    uint2* zC2 = reinterpret_cast<uint2*>(zC);

    // load h -> fp16 into zA rows 3..352
    const float4* hg = reinterpret_cast<const float4*>(src + (size_t)doc*LSEQ*CLS);
    for (int i = t; i < LSEQ*CLS/4; i += GT) {
        float4 v = hg[i];
        __half2 lo = __floats2half2_rn(v.x, v.y);
        __half2 hi = __floats2half2_rn(v.z, v.w);
        uint2 u;
        u.x = *reinterpret_cast<uint32_t*>(&lo);
        u.y = *reinterpret_cast<uint32_t*>(&hi);
        zA2[i + 15] = u;
    }
    const float* Wg = gat_W + ((size_t)layer*HEADS + hd)*CLS*CLS;
    for (int i = t; i < CLS*CLS; i += GT) Wb[i] = Wg[i];
    if (t >= GT-32 && t < GT-32+CLS) {
        int c = t - (GT-32);
        asb[c] = a_src[(layer*HEADS + hd)*CLS + c];
        adb[c] = a_dst[(layer*HEADS + hd)*CLS + c];
    }
    // zero halos
    if (t >= GT-128 && t < GT-128+90) {
        int r0 = t - (GT-128);
        int buf = r0 / 30, r = r0 % 30;
        uint2* z = (buf == 0) ? zA2 : (buf == 1) ? zB2 : zC2;
        int idx = (r < 15) ? r : (ZH/4 - 30 + r);
        z[idx] = make_uint2(0u, 0u);
    }
    __syncthreads();

    // projection (in-place on zA): z0[p] = h[p] @ W; es/ed scores
    for (int p = t; p < LSEQ; p += GT) {
        uint2 hr[5];
        #pragma unroll
        for (int q = 0; q < 5; q++) hr[q] = zA2[(p+3)*5 + q];
        const __half* hh = reinterpret_cast<const __half*>(hr);
        float zr[CLS];
        #pragma unroll
        for (int c = 0; c < CLS; c++) zr[c] = 0.f;
        #pragma unroll
        for (int c2 = 0; c2 < CLS; c2++) {
            float hv = __half2float(hh[c2]);
            #pragma unroll
            for (int c = 0; c < CLS; c++)
                zr[c] = fmaf(hv, Wb[c2*CLS + c], zr[c]);
        }
        float es = 0.f, ed = 0.f;
        #pragma unroll
        for (int c = 0; c < CLS; c++) {
            es = fmaf(zr[c], asb[c], es);
            ed = fmaf(zr[c], adb[c], ed);
        }
        esb[p] = es; edb[p] = ed;
        #pragma unroll
        for (int q = 0; q < 5; q++) {
            __half2 lo = __floats2half2_rn(zr[q*4+0], zr[q*4+1]);
            __half2 hi = __floats2half2_rn(zr[q*4+2], zr[q*4+3]);
            uint2 u;
            u.x = *reinterpret_cast<uint32_t*>(&lo);
            u.y = *reinterpret_cast<uint32_t*>(&hi);
            zA2[(p+3)*5 + q] = u;
        }
    }
    __syncthreads();

    // banded softmax -> att half2 planes
    for (int p = t; p < LSEQ; p += GT) {
        float ed = edb[p];
        float e[WIN], m = -1e30f;
        #pragma unroll
        for (int w = 0; w < WIN; w++) {
            int j = p - NGW + w;
            bool valid = (j >= 0) & (j < LSEQ);
            int jj = valid ? j : p;
            float ev = esb[jj] + ed;
            ev = ev > 0.f ? ev : 0.2f*ev;
            e[w] = valid ? ev : -1e30f;
            m = fmaxf(m, e[w]);
        }
        float ex[WIN], s = 0.f;
        #pragma unroll
        for (int w = 0; w < WIN; w++) {
            ex[w] = (e[w] > -1e29f) ? expf(e[w] - m) : 0.f;
            s += ex[w];
        }
        float inv = 1.f / (s + 1e-9f);
        __half2 w01 = __floats2half2_rn(ex[0]*inv, ex[1]*inv);
        __half2 w23 = __floats2half2_rn(ex[2]*inv, ex[3]*inv);
        __half2 w45 = __floats2half2_rn(ex[4]*inv, ex[5]*inv);
        __half2 w6x = __floats2half2_rn(ex[6]*inv, 0.f);
        uint2 u0, u1;
        u0.x = *reinterpret_cast<uint32_t*>(&w01);
        u0.y = *reinterpret_cast<uint32_t*>(&w23);
        u1.x = *reinterpret_cast<uint32_t*>(&w45);
        u1.y = *reinterpret_cast<uint32_t*>(&w6x);
        a0h[p] = u0;
        a1h[p] = u1;
    }
    __syncthreads();

    // hops: half2 stencil FMAs; fp32 blend + ELU
    float* dsb = dst + (size_t)doc*LSEQ*CLS;
    #pragma unroll
    for (int hop = 0; hop < KHOPS; hop++) {
        const uint2* zin2 = (hop == 0) ? zA2 : ((hop == 1) ? zB2 : zC2);
        uint2*      zout2 = (hop == 0) ? zB2 : zC2;
        for (int j = t; j < LSEQ*CLS/4; j += GT) {
            int p = j / 5;
            int g = j - p*5;
            uint2 ua = a0h[p], ub = a1h[p];
            __half2 a01 = *reinterpret_cast<__half2*>(&ua.x);
            __half2 a23 = *reinterpret_cast<__half2*>(&ua.y);
            __half2 a45 = *reinterpret_cast<__half2*>(&ub.x);
            __half2 a6x = *reinterpret_cast<__half2*>(&ub.y);
            __half2 b0 = __low2half2(a01), b1 = __high2half2(a01);
            __half2 b2 = __low2half2(a23), b3 = __high2half2(a23);
            __half2 b4 = __low2half2(a45), b5 = __high2half2(a45);
            __half2 b6 = __low2half2(a6x);
            const uint2* zi = zin2 + p*5 + g;
            uint2 t0 = zi[0],  t1 = zi[5],  t2 = zi[10], t3 = zi[15];
            uint2 t4 = zi[20], t5 = zi[25], t6 = zi[30];
            #define H2(u) (*reinterpret_cast<__half2*>(&(u)))
            __half2 accL = __hmul2(b0, H2(t0.x));
            __half2 accH = __hmul2(b0, H2(t0.y));
            accL = __hfma2(b1, H2(t1.x), accL); accH = __hfma2(b1, H2(t1.y), accH);
            accL = __hfma2(b2, H2(t2.x), accL); accH = __hfma2(b2, H2(t2.y), accH);
            accL = __hfma2(b3, H2(t3.x), accL); accH = __hfma2(b3, H2(t3.y), accH);
            accL = __hfma2(b4, H2(t4.x), accL); accH = __hfma2(b4, H2(t4.y), accH);
            accL = __hfma2(b5, H2(t5.x), accL); accH = __hfma2(b5, H2(t5.y), accH);
            accL = __hfma2(b6, H2(t6.x), accL); accH = __hfma2(b6, H2(t6.y), accH);
            #undef H2
            float2 aL = __half22float2(accL);
            float2 aH = __half22float2(accH);
            uint2 uz = zA2[(p+3)*5 + g];
            float2 zlo = __half22float2(*reinterpret_cast<__half2*>(&uz.x));
            float2 zhi = __half22float2(*reinterpret_cast<__half2*>(&uz.y));
            float4 v;
            v.x = fmaf(1.f - ALPHA, aL.x, ALPHA*zlo.x);
            v.y = fmaf(1.f - ALPHA, aL.y, ALPHA*zlo.y);
            v.z = fmaf(1.f - ALPHA, aH.x, ALPHA*zhi.x);
            v.w = fmaf(1.f - ALPHA, aH.y, ALPHA*zhi.y);
            if (hop == KHOPS-1) {
                float* o = dsb + p*CLS + g*4;
                float ex0 = (v.x > 0.f) ? v.x : expm1f(v.x);
                float ex1 = (v.y > 0.f) ? v.y : expm1f(v.y);
                float ex2 = (v.z > 0.f) ? v.z : expm1f(v.z);
                float ex3 = (v.w > 0.f) ? v.w : expm1f(v.w);
                atomicAdd(o+0, ex0 * (1.f/HEADS));
                atomicAdd(o+1, ex1 * (1.f/HEADS));
                atomicAdd(o+2, ex2 * (1.f/HEADS));
                atomicAdd(o+3, ex3 * (1.f/HEADS));
            } else {
                __half2 lo = __floats2half2_rn(v.x, v.y);
                __half2 hi = __floats2half2_rn(v.z, v.w);
                uint2 u;
                u.x = *reinterpret_cast<uint32_t*>(&lo);
                u.y = *reinterpret_cast<uint32_t*>(&hi);
                zout2[(p+3)*5 + g] = u;
            }
        }
        if (hop < KHOPS-1) __syncthreads();
    }
}

// ---------------- K4: gated readout ----------------
__global__ __launch_bounds__(256) void k_readout(
    const float* __restrict__ w_gate, const float* __restrict__ b_gate,
    float* __restrict__ out)
{
    __shared__ float wg[CLS];
    __shared__ float sred[240];
    const int t = threadIdx.x;
    if (t < CLS) wg[t] = w_gate[t];
    __syncthreads();
    const int doc = blockIdx.x;
    const float bg = b_gate[0];
    float acc = 0.f;
    if (t < 240) {
        int c = t % CLS, r = t / CLS;
        for (int p = r; p < LSEQ; p += 12) {
            const float* hr = g_h + (doc*LSEQ + p)*CLS;
            float dot = bg;
            #pragma unroll
            for (int k = 0; k < CLS; k++) dot = fmaf(hr[k], wg[k], dot);
            float gate = 1.f / (1.f + expf(-dot));
            acc = fmaf(gate, hr[c], acc);
        }
        sred[t] = acc;
    }
    __syncthreads();
    if (t < CLS) {
        float s = 0.f;
        #pragma unroll
        for (int r = 0; r < 12; r++) s += sred[r*CLS + t];
        out[doc*CLS + t] = s;
    }
}

// ---------------- launch ----------------
extern "C" void kernel_launch(void* const* d_in, const int* in_sizes, int n_in,
                              void* d_out, int out_size)
{
    const int*   node_ids = (const int*)  d_in[0];
    const float* emb    = (const float*) d_in[4];
    const float* W1     = (const float*) d_in[5];
    const float* b1     = (const float*) d_in[6];
    const float* W2     = (const float*) d_in[7];
    const float* b2     = (const float*) d_in[8];
    const float* gat_W  = (const float*) d_in[9];
    const float* a_src  = (const float*) d_in[10];
    const float* a_dst  = (const float*) d_in[11];
    const float* w_gate = (const float*) d_in[12];
    const float* b_gate = (const float*) d_in[13];
    float* out = (float*)d_out;

    cudaFuncSetAttribute(k_gemm1tc,
        cudaFuncAttributeMaxDynamicSharedMemorySize, GEMM_SMEM);
    cudaFuncSetAttribute(k_gat,
        cudaFuncAttributeMaxDynamicSharedMemorySize, GAT_SMEM);

    k_prepw<<<DIM, 256>>>(W1);                                           // 768
    k_gemm1tc<<<NNODES/TM, 256, GEMM_SMEM>>>(node_ids, emb, b1, W2, b2); // 280
    for (int l = 0; l < LAYERS; l++) {
        if (l > 0) k_zero<<<NNODES*CLS/1024, 256>>>(0);                  // zero g_h
        k_gat<<<B_DOCS*HEADS, GT, GAT_SMEM>>>(gat_W, a_src, a_dst, l);   // 1024
    }
    k_readout<<<B_DOCS, 256>>>(w_gate, b_gate, out);
}